// round 13
// baseline (speedup 1.0000x reference)
#include <cuda_runtime.h>
#include <cuda_fp16.h>
#include <math.h>
#include <stdint.h>

#define B_      4
#define S_      1024
#define E_      1024
#define NHEADS  16
#define H_      64
#define NH_     1024
#define F_      4096
#define R_      2048

// ---------------- scratch (static device globals) ----------------
__device__ __half g_xh[4194304];       // [B,S,E]
__device__ __half g_rpeh[8388608];     // [B,R,E]
__device__ __half g_qkv[12582912];     // [B,S,3NH]: cols 1024..2047=K, 2048..3071=V
__device__ __half g_qc[4194304];
__device__ __half g_qp[4194304];
__device__ __half g_r[8388608];
__device__ __half g_vt[4194304];       // [B,N,H,S]
__device__ __half g_attn[4194304];
__device__ float  g_h1[4194304];
__device__ __half g_h1h[4194304];
__device__ __half g_inner[16777216];
__device__ float  g_tmp[4194304];
__device__ __half g_WqkvT[3145728];    // [3NH, E]
__device__ __half g_WrT[1048576];
__device__ __half g_WoT[1048576];
__device__ __half g_WiT[4194304];
__device__ __half g_WoutT[4194304];

// ---------------- helpers ----------------
__device__ __forceinline__ uint32_t smem_u32(const void* p) {
    uint32_t a;
    asm("{ .reg .u64 t; cvta.to.shared.u64 t, %1; cvt.u32.u64 %0, t; }" : "=r"(a) : "l"(p));
    return a;
}
__device__ __forceinline__ void cpasync16(uint32_t s, const void* g) {
    asm volatile("cp.async.cg.shared.global [%0], [%1], 16;" :: "r"(s), "l"(g));
}
#define CP_COMMIT() asm volatile("cp.async.commit_group;" ::: "memory")
#define CP_WAIT(n)  asm volatile("cp.async.wait_group %0;" :: "n"(n) : "memory")

#define LDM4(r0, r1, r2, r3, a)                                                     \
    asm volatile("ldmatrix.sync.aligned.m8n8.x4.shared.b16 {%0,%1,%2,%3}, [%4];"    \
                 : "=r"(r0), "=r"(r1), "=r"(r2), "=r"(r3) : "r"(a))

#define MMA16816(c, a, b)                                                           \
    asm volatile("mma.sync.aligned.m16n8k16.row.col.f32.f16.f16.f32 "               \
                 "{%0,%1,%2,%3},{%4,%5,%6,%7},{%8,%9},{%0,%1,%2,%3};"               \
                 : "+f"((c)[0]), "+f"((c)[1]), "+f"((c)[2]), "+f"((c)[3])           \
                 : "r"((a)[0]), "r"((a)[1]), "r"((a)[2]), "r"((a)[3]),              \
                   "r"((b)[0]), "r"((b)[1]))

// exp on FMA/ALU pipes; common-mode error cancels in softmax normalization.
__device__ __forceinline__ float fast_exp(float x) {
    float t = fmaxf(x * 1.44269504f, -126.f);
    float fl = floorf(t);
    float f = t - fl;
    float p = fmaf(f, 0.0792345f, 0.2248712f);
    p = fmaf(f, p, 0.6958943f);
    p = fmaf(f, p, 1.0f);
    return __int_as_float(__float_as_int(p) + (((int)fl) << 23));
}

// ---------------- fp16 tensor-core GEMM, K-chunk 64, 3-stage ring ---------------
// EPI 0: store (+bias/relu/scale), OUTH picks half/float.
// EPI 2: QKV epilogue — col<NH_: qc=(v+cb)/8, qp=(v+pb)/8 (half); else store half.
#define LDSG 72
#define HG_SMEM128 (3 * (128 + 128) * LDSG * 2)
#define HG_SMEM256 (3 * (128 + 256) * LDSG * 2)
template<int BN, int WRM, int WRN, int EPI, int OUTH>
__global__ __launch_bounds__(256, (BN == 128 ? 2 : 1)) void hgemm(
    const __half* __restrict__ A, const __half* __restrict__ Bm,
    void* __restrict__ Cv, const float* __restrict__ bias,
    const float* __restrict__ pb, __half* __restrict__ qcp, __half* __restrict__ qpp,
    int K, int lda, int ldb, int ldc, int zdiv,
    long long As1, long long As2, long long Bs1, long long Bs2,
    long long Cs1, long long Cs2, int relu, float scale)
{
    constexpr int BM = 128;
    constexpr int MW = BM / WRM, NW = BN / WRN;
    constexpr int MT = MW / 16, NPAIR = NW / 16, NT = NW / 8;
    extern __shared__ __half hsm[];
    __half* sA = hsm;
    __half* sB = hsm + 3 * BM * LDSG;

    const int bm = blockIdx.y * BM, bn = blockIdx.x * BN;
    {
        int z = blockIdx.z, zq = z / zdiv, zr = z % zdiv;
        A  += zq * As1 + zr * As2;
        Bm += zq * Bs1 + zr * Bs2;
    }
    const int tid = threadIdx.x, lane = tid & 31, wid = tid >> 5;
    const int wm = (wid / WRN) * MW, wn = (wid % WRN) * NW;

    float cf[MT][NT][4];
#pragma unroll
    for (int i = 0; i < MT; i++)
#pragma unroll
        for (int j = 0; j < NT; j++)
#pragma unroll
            for (int e = 0; e < 4; e++) cf[i][j][e] = 0.f;

    auto stage = [&](int c, int sx) {
        __half* dA = sA + sx * BM * LDSG;
        __half* dB = sB + sx * BN * LDSG;
#pragma unroll
        for (int i = 0; i < BM * 8 / 256; i++) {
            int id = tid + i * 256, row = id >> 3, ch = id & 7;
            cpasync16(smem_u32(dA + row * LDSG + ch * 8),
                      A + (long long)(bm + row) * lda + c * 64 + ch * 8);
        }
#pragma unroll
        for (int i = 0; i < BN * 8 / 256; i++) {
            int id = tid + i * 256, row = id >> 3, ch = id & 7;
            cpasync16(smem_u32(dB + row * LDSG + ch * 8),
                      Bm + (long long)(bn + row) * ldb + c * 64 + ch * 8);
        }
        CP_COMMIT();
    };

    const int nkt = K >> 6;
    stage(0, 0);
    stage(1, 1);
    int cbuf = 0, pbuf = 2;
    for (int c = 0; c < nkt; c++) {
        CP_WAIT(1);
        __syncthreads();
        if (c + 2 < nkt) stage(c + 2, pbuf);
        else CP_COMMIT();
        const uint32_t a0 = smem_u32(sA + cbuf * BM * LDSG);
        const uint32_t b0 = smem_u32(sB + cbuf * BN * LDSG);
#pragma unroll
        for (int ks = 0; ks < 4; ks++) {
            uint32_t af[MT][4], bf[NT][2];
#pragma unroll
            for (int mt = 0; mt < MT; mt++) {
                uint32_t ad = a0 + ((wm + mt * 16 + (lane & 15)) * LDSG
                                    + ks * 16 + (lane >> 4) * 8) * 2;
                LDM4(af[mt][0], af[mt][1], af[mt][2], af[mt][3], ad);
            }
#pragma unroll
            for (int p = 0; p < NPAIR; p++) {
                int rn = wn + p * 16 + (lane & 7) + ((lane >> 4) << 3);
                uint32_t bd = b0 + (rn * LDSG + ks * 16 + ((lane >> 3) & 1) * 8) * 2;
                uint32_t r0, r1, r2, r3;
                LDM4(r0, r1, r2, r3, bd);
                bf[2 * p][0] = r0; bf[2 * p][1] = r1;
                bf[2 * p + 1][0] = r2; bf[2 * p + 1][1] = r3;
            }
#pragma unroll
            for (int mt = 0; mt < MT; mt++)
#pragma unroll
                for (int nt = 0; nt < NT; nt++)
                    MMA16816(cf[mt][nt], af[mt], bf[nt]);
        }
        cbuf = cbuf == 2 ? 0 : cbuf + 1;
        pbuf = pbuf == 2 ? 0 : pbuf + 1;
    }

    long long coff;
    {
        int z = blockIdx.z, zq = z / zdiv, zr = z % zdiv;
        coff = zq * Cs1 + zr * Cs2;
    }
#pragma unroll
    for (int mt = 0; mt < MT; mt++) {
#pragma unroll
        for (int nt = 0; nt < NT; nt++) {
            int r = bm + wm + mt * 16 + (lane >> 2);
            int col = bn + wn + nt * 8 + (lane & 3) * 2;
#pragma unroll
            for (int e2 = 0; e2 < 2; e2++) {
                int row = r + 8 * e2;
                float v0 = cf[mt][nt][e2 * 2] * scale;
                float v1 = cf[mt][nt][e2 * 2 + 1] * scale;
                if (EPI == 2) {
                    if (col < NH_) {
                        float c0 = bias[col], c1 = bias[col + 1];
                        float p0 = pb[col],  p1 = pb[col + 1];
                        *(__half2*)(qcp + (long long)row * NH_ + col) =
                            __floats2half2_rn((v0 + c0) * 0.125f, (v1 + c1) * 0.125f);
                        *(__half2*)(qpp + (long long)row * NH_ + col) =
                            __floats2half2_rn((v0 + p0) * 0.125f, (v1 + p1) * 0.125f);
                    } else {
                        __half* Ch = (__half*)Cv;
                        *(__half2*)(Ch + (long long)row * ldc + col) =
                            __floats2half2_rn(v0, v1);
                    }
                } else {
                    if (bias) { v0 += bias[col]; v1 += bias[col + 1]; }
                    if (relu) { v0 = fmaxf(v0, 0.f); v1 = fmaxf(v1, 0.f); }
                    if (OUTH) {
                        __half* Ch = (__half*)Cv + coff;
                        *(__half2*)(Ch + (long long)row * ldc + col) =
                            __floats2half2_rn(v0, v1);
                    } else {
                        float* Cf = (float*)Cv + coff;
                        *(float2*)(Cf + (long long)row * ldc + col) = make_float2(v0, v1);
                    }
                }
            }
        }
    }
}

// ---------------- flash attention: cross-iteration staged K/R/V pipeline --------
#define LDQ_  72
#define LDV_  136
#define LDS_S 132
#define LDP_  136
#define FL_SMEM (3*128*LDQ_*2 + 64*LDV_*2 + 256*LDQ_*2 + 128*LDS_S*4 + 128*LDP_*2 + 3*128*4)

__global__ __launch_bounds__(256, 1) void flash_k(
    const __half* __restrict__ qc, const __half* __restrict__ qp,
    const __half* __restrict__ kk, const __half* __restrict__ vt,
    const __half* __restrict__ rr, __half* __restrict__ attn, int kstr)
{
    extern __shared__ char smraw[];
    __half* sQc = (__half*)smraw;
    __half* sQp = sQc + 128 * LDQ_;
    __half* sK  = sQp + 128 * LDQ_;
    __half* sV  = sK  + 128 * LDQ_;
    __half* sR  = sV  + 64 * LDV_;
    float*  sS  = (float*)(sR + 256 * LDQ_);
    __half* sP  = (__half*)(sS + 128 * LDS_S);
    float*  sM  = (float*)(sP + 128 * LDP_);
    float*  sL  = sM + 128;
    float*  sAl = sL + 128;

    const int it = blockIdx.x, z = blockIdx.y;
    const int b = z >> 4, n = z & 15;
    const int i0 = it * 128;
    const int tid = threadIdx.x, lane = tid & 31, wid = tid >> 5;
    const int wm = wid * 16;

    int ntlo0 = (105 - wm + 7) >> 3; if (ntlo0 < 0) ntlo0 = 0;
    int nthi1 = (126 - wm) >> 3;

    const __half* qcb = qc + (long long)b * S_ * NH_ + n * H_;
    const __half* qpb = qp + (long long)b * S_ * NH_ + n * H_;
    const __half* kb  = kk + (long long)b * S_ * kstr + n * H_;
    const __half* vtb = vt + (long long)z * H_ * S_;
    const __half* rb  = rr + (long long)b * R_ * NH_ + n * H_;

    auto stageK = [&](int jt) {
        const int j0 = jt * 128;
        if (jt < 8) {
#pragma unroll
            for (int i = 0; i < 4; i++) {
                int id = tid + i * 256, row = id >> 3, ch = id & 7;
                cpasync16(smem_u32(sK + row * LDQ_ + ch * 8),
                          kb + (long long)(j0 + row) * kstr + ch * 8);
            }
        }
        CP_COMMIT();
    };
    auto stageR = [&](int jt) {
        const int base = S_ + jt * 128 - i0 - 127;
        if (jt < 8) {
#pragma unroll
            for (int i = 0; i < 8; i++) {
                int id = tid + i * 256, row = id >> 3, ch = id & 7;
                int grow = base + row; grow = grow < R_ ? grow : R_ - 1;
                cpasync16(smem_u32(sR + row * LDQ_ + ch * 8),
                          rb + (long long)grow * NH_ + ch * 8);
            }
        }
        CP_COMMIT();
    };
    auto stageV = [&](int jt) {
        const int j0 = jt * 128;
        if (jt < 8) {
#pragma unroll
            for (int i = 0; i < 4; i++) {
                int id = tid + i * 256, row = id >> 4, ch = id & 15;
                cpasync16(smem_u32(sV + row * LDV_ + ch * 8),
                          vtb + (long long)row * S_ + j0 + ch * 8);
            }
        }
        CP_COMMIT();
    };

#pragma unroll
    for (int i = 0; i < 4; i++) {
        int id = tid + i * 256, row = id >> 3, ch = id & 7;
        cpasync16(smem_u32(sQc + row * LDQ_ + ch * 8),
                  qcb + (long long)(i0 + row) * NH_ + ch * 8);
        cpasync16(smem_u32(sQp + row * LDQ_ + ch * 8),
                  qpb + (long long)(i0 + row) * NH_ + ch * 8);
    }
    stageK(0);
    stageR(0);
    stageV(0);
    if (tid < 128) { sM[tid] = -1e30f; sL[tid] = 0.f; }

    float of[8][4];
#pragma unroll
    for (int nt = 0; nt < 8; nt++)
#pragma unroll
        for (int e = 0; e < 4; e++) of[nt][e] = 0.f;

    const uint32_t aQc = smem_u32(sQc), aQp = smem_u32(sQp);
    const uint32_t aK = smem_u32(sK), aV = smem_u32(sV);
    const uint32_t aR = smem_u32(sR), aP = smem_u32(sP);

    for (int jt = 0; jt < 8; jt++) {
        CP_WAIT(2);
        __syncthreads();

        // ---- content scores -> sS ----
        float cf[16][4];
#pragma unroll
        for (int nt = 0; nt < 16; nt++)
#pragma unroll
            for (int e = 0; e < 4; e++) cf[nt][e] = 0.f;
#pragma unroll
        for (int ks = 0; ks < 4; ks++) {
            uint32_t af[4], bf[16][2];
            LDM4(af[0], af[1], af[2], af[3],
                 aQc + ((wm + (lane & 15)) * LDQ_ + ks * 16 + (lane >> 4) * 8) * 2);
#pragma unroll
            for (int p = 0; p < 8; p++) {
                int rn = p * 16 + (lane & 7) + ((lane >> 4) << 3);
                uint32_t r0, r1, r2, r3;
                LDM4(r0, r1, r2, r3, aK + (rn * LDQ_ + ks * 16 + ((lane >> 3) & 1) * 8) * 2);
                bf[2 * p][0] = r0; bf[2 * p][1] = r1;
                bf[2 * p + 1][0] = r2; bf[2 * p + 1][1] = r3;
            }
#pragma unroll
            for (int nt = 0; nt < 16; nt++) MMA16816(cf[nt], af, bf[nt]);
        }
#pragma unroll
        for (int nt = 0; nt < 16; nt++) {
            int c0 = nt * 8 + (lane & 3) * 2;
#pragma unroll
            for (int e2 = 0; e2 < 2; e2++) {
                int row = wm + (lane >> 2) + 8 * e2;
                *(float2*)&sS[row * LDS_S + c0] = make_float2(cf[nt][e2 * 2], cf[nt][e2 * 2 + 1]);
            }
        }

        CP_WAIT(1);
        __syncthreads();
        stageK(jt + 1);

        // ---- position scores, band tiles only ----
#pragma unroll
        for (int halfg = 0; halfg < 2; halfg++) {
            int g0 = halfg * 128;
            int lo = halfg == 0 ? ntlo0 : 0;
            int hi = halfg == 0 ? 15 : nthi1;
#pragma unroll
            for (int nt = 0; nt < 16; nt++)
#pragma unroll
                for (int e = 0; e < 4; e++) cf[nt][e] = 0.f;
#pragma unroll
            for (int ks = 0; ks < 4; ks++) {
                uint32_t af[4], bf[16][2];
                LDM4(af[0], af[1], af[2], af[3],
                     aQp + ((wm + (lane & 15)) * LDQ_ + ks * 16 + (lane >> 4) * 8) * 2);
#pragma unroll
                for (int p = 0; p < 8; p++) {
                    if (2 * p + 1 < lo || 2 * p > hi) continue;
                    int rn = g0 + p * 16 + (lane & 7) + ((lane >> 4) << 3);
                    uint32_t r0, r1, r2, r3;
                    LDM4(r0, r1, r2, r3, aR + (rn * LDQ_ + ks * 16 + ((lane >> 3) & 1) * 8) * 2);
                    bf[2 * p][0] = r0; bf[2 * p][1] = r1;
                    bf[2 * p + 1][0] = r2; bf[2 * p + 1][1] = r3;
                }
#pragma unroll
                for (int nt = 0; nt < 16; nt++) {
                    if (nt < lo || nt > hi) continue;
                    MMA16816(cf[nt], af, bf[nt]);
                }
            }
#pragma unroll
            for (int nt = 0; nt < 16; nt++) {
                if (nt < lo || nt > hi) continue;
#pragma unroll
                for (int e = 0; e < 4; e++) {
                    int li = wm + (lane >> 2) + 8 * (e >> 1);
                    int g  = g0 + nt * 8 + (lane & 3) * 2 + (e & 1);
                    int lj = g - 127 + li;
                    if (lj >= 0 && lj < 128) sS[li * LDS_S + lj] += cf[nt][e];
                }
            }
            __syncwarp();
        }

        CP_WAIT(1);
        __syncthreads();
        stageR(jt + 1);

        // ---- online softmax ----
        {
            int rloc = wm + (lane >> 1), hf = lane & 1;
            float* srow = &sS[rloc * LDS_S + hf * 64];
            float4* srow4 = (float4*)srow;
            float m0 = -1e30f, m1 = -1e30f, m2 = -1e30f, m3 = -1e30f;
#pragma unroll
            for (int c = 0; c < 16; c += 2) {
                float4 a = srow4[c], bq = srow4[c + 1];
                m0 = fmaxf(m0, fmaxf(a.x, a.y));
                m1 = fmaxf(m1, fmaxf(a.z, a.w));
                m2 = fmaxf(m2, fmaxf(bq.x, bq.y));
                m3 = fmaxf(m3, fmaxf(bq.z, bq.w));
            }
            float mx = fmaxf(fmaxf(m0, m1), fmaxf(m2, m3));
            mx = fmaxf(mx, __shfl_xor_sync(0xffffffffu, mx, 1));
            float mold = sM[rloc];
            float mnew = fmaxf(mold, mx);
            float alpha = fast_exp(mold - mnew);
            float s0 = 0.f, s1 = 0.f;
            __half* prow = &sP[rloc * LDP_ + hf * 64];
#pragma unroll
            for (int c = 0; c < 16; c++) {
                float4 a = srow4[c];
                float p0 = fast_exp(a.x - mnew);
                float p1 = fast_exp(a.y - mnew);
                float p2 = fast_exp(a.z - mnew);
                float p3 = fast_exp(a.w - mnew);
                s0 += p0 + p1;
                s1 += p2 + p3;
                *(__half2*)&prow[c * 4]     = __floats2half2_rn(p0, p1);
                *(__half2*)&prow[c * 4 + 2] = __floats2half2_rn(p2, p3);
            }
            float sum = s0 + s1;
            sum += __shfl_xor_sync(0xffffffffu, sum, 1);
            if (hf == 0) {
                sL[rloc] = sL[rloc] * alpha + sum;
                sM[rloc] = mnew;
                sAl[rloc] = alpha;
            }
        }
        __syncwarp();

        // ---- rescale O, PV mma ----
#pragma unroll
        for (int e2 = 0; e2 < 2; e2++) {
            float al = sAl[wm + (lane >> 2) + 8 * e2];
#pragma unroll
            for (int nt = 0; nt < 8; nt++) {
                of[nt][e2 * 2]     *= al;
                of[nt][e2 * 2 + 1] *= al;
            }
        }
#pragma unroll
        for (int ks = 0; ks < 8; ks++) {
            uint32_t af[4], bfv[8][2];
            LDM4(af[0], af[1], af[2], af[3],
                 aP + ((wm + (lane & 15)) * LDP_ + ks * 16 + (lane >> 4) * 8) * 2);
#pragma unroll
            for (int p = 0; p < 4; p++) {
                int rn = p * 16 + (lane & 7) + ((lane >> 4) << 3);
                uint32_t r0, r1, r2, r3;
                LDM4(r0, r1, r2, r3, aV + (rn * LDV_ + ks * 16 + ((lane >> 3) & 1) * 8) * 2);
                bfv[2 * p][0] = r0; bfv[2 * p][1] = r1;
                bfv[2 * p + 1][0] = r2; bfv[2 * p + 1][1] = r3;
            }
#pragma unroll
            for (int nt = 0; nt < 8; nt++) MMA16816(of[nt], af, bfv[nt]);
        }
        __syncthreads();
        stageV(jt + 1);
    }

#pragma unroll
    for (int e2 = 0; e2 < 2; e2++) {
        int li = wm + (lane >> 2) + 8 * e2;
        float inv = 1.0f / sL[li];
        long long rowg = (long long)(b * S_ + i0 + li) * NH_ + n * H_;
#pragma unroll
        for (int nt = 0; nt < 8; nt++) {
            int col = nt * 8 + (lane & 3) * 2;
            *(__half2*)(attn + rowg + col) =
                __floats2half2_rn(of[nt][e2 * 2] * inv, of[nt][e2 * 2 + 1] * inv);
        }
    }
}

// ---------------- fp32 -> fp16 copy ----------------
__global__ __launch_bounds__(256) void f2h_k(const float* __restrict__ in,
                                             __half* __restrict__ out)
{
    long long i = (long long)blockIdx.x * 256 + threadIdx.x;
    float4 v = ((const float4*)in)[i];
    ((__half2*)out)[i * 2]     = __floats2half2_rn(v.x, v.y);
    ((__half2*)out)[i * 2 + 1] = __floats2half2_rn(v.z, v.w);
}

// ---------------- fp32 transpose -> fp16 ----------------
__global__ void transpose_h16(const float* __restrict__ in, __half* __restrict__ out,
                              int rows, int cols)
{
    __shared__ float tile[32][33];
    int r0 = blockIdx.y * 32, c0 = blockIdx.x * 32;
    int tx = threadIdx.x, ty = threadIdx.y;
#pragma unroll
    for (int i = 0; i < 4; i++)
        tile[ty + i * 8][tx] = in[(long long)(r0 + ty + i * 8) * cols + c0 + tx];
    __syncthreads();
#pragma unroll
    for (int i = 0; i < 4; i++)
        out[(long long)(c0 + ty + i * 8) * rows + r0 + tx] = __float2half_rn(tile[tx][ty + i * 8]);
}

// ---------------- per-head half transpose ----------------
__global__ void transpose_vh(const __half* __restrict__ in, __half* __restrict__ out,
                             int rows, int instr)
{
    __shared__ __half tile[32][34];
    int z = blockIdx.z, b = z >> 4, n = z & 15;
    const __half* ip = in + (long long)b * rows * instr + n * H_;
    __half* op = out + (long long)z * H_ * rows;
    int r0 = blockIdx.x * 32, h0 = blockIdx.y * 32;
    int tx = threadIdx.x, ty = threadIdx.y;
#pragma unroll
    for (int i = 0; i < 4; i++)
        tile[ty + i * 8][tx] = ip[(long long)(r0 + ty + i * 8) * instr + h0 + tx];
    __syncthreads();
#pragma unroll
    for (int i = 0; i < 4; i++)
        op[(long long)(h0 + ty + i * 8) * rows + r0 + tx] = tile[tx][ty + i * 8];
}

// ---------------- residual + LayerNorm (optional fp16 copy) ---------------------
__global__ __launch_bounds__(256) void ln_k(
    const float* __restrict__ a, const float* __restrict__ res,
    const float* __restrict__ g, const float* __restrict__ bt,
    float* __restrict__ o, __half* __restrict__ oh)
{
    __shared__ float red[16];
    long long row = blockIdx.x;
    int t = threadIdx.x;
    float4 va = *((const float4*)(a + row * 1024) + t);
    float4 vr = *((const float4*)(res + row * 1024) + t);
    float4 x;
    x.x = va.x + vr.x; x.y = va.y + vr.y; x.z = va.z + vr.z; x.w = va.w + vr.w;
    float s  = x.x + x.y + x.z + x.w;
    float q2 = x.x * x.x + x.y * x.y + x.z * x.z + x.w * x.w;
#pragma unroll
    for (int off = 16; off; off >>= 1) {
        s  += __shfl_xor_sync(0xffffffffu, s, off);
        q2 += __shfl_xor_sync(0xffffffffu, q2, off);
    }
    if ((t & 31) == 0) { red[t >> 5] = s; red[8 + (t >> 5)] = q2; }
    __syncthreads();
    if (t == 0) {
        float ss = red[0], qq = red[8];
#pragma unroll
        for (int i = 1; i < 8; i++) { ss += red[i]; qq += red[8 + i]; }
        red[0] = ss; red[8] = qq;
    }
    __syncthreads();
    float mu  = red[0] * (1.f / 1024.f);
    float var = red[8] * (1.f / 1024.f) - mu * mu;
    float rs = rsqrtf(var + 1e-12f);
    float4 gg = *((const float4*)g + t);
    float4 bb = *((const float4*)bt + t);
    float4 y;
    y.x = (x.x - mu) * rs * gg.x + bb.x;
    y.y = (x.y - mu) * rs * gg.y + bb.y;
    y.z = (x.z - mu) * rs * gg.z + bb.z;
    y.w = (x.w - mu) * rs * gg.w + bb.w;
    *((float4*)(o + row * 1024) + t) = y;
    if (oh) {
        __half2* ph = (__half2*)(oh + row * 1024);
        ph[2 * t]     = __floats2half2_rn(y.x, y.y);
        ph[2 * t + 1] = __floats2half2_rn(y.z, y.w);
    }
}

// ---------------- driver --------------------------------------------------------
extern "C" void kernel_launch(void* const* d_in, const int* in_sizes, int n_in,
                              void* d_out, int out_size)
{
    const float* x    = (const float*)d_in[0];
    const float* cb   = (const float*)d_in[1];
    const float* pb   = (const float*)d_in[2];
    const float* rpe  = (const float*)d_in[3];
    const float* Wq   = (const float*)d_in[4];
    const float* Wk   = (const float*)d_in[5];
    const float* Wv   = (const float*)d_in[6];
    const float* Wr   = (const float*)d_in[7];
    const float* Wo   = (const float*)d_in[8];
    const float* ln1g = (const float*)d_in[9];
    const float* ln1b = (const float*)d_in[10];
    const float* Wi   = (const float*)d_in[11];
    const float* bi   = (const float*)d_in[12];
    const float* Wout = (const float*)d_in[13];
    const float* bout = (const float*)d_in[14];
    const float* ln2g = (const float*)d_in[15];
    const float* ln2b = (const float*)d_in[16];
    float* out = (float*)d_out;

    __half *xh,*rpeh,*qkv,*qc,*qp,*r,*vt,*attn,*h1h,*inner;
    __half *WqkvT,*WrT,*WoT,*WiT,*WoutT;
    float *h1,*tmp;
    cudaGetSymbolAddress((void**)&xh, g_xh);      cudaGetSymbolAddress((void**)&rpeh, g_rpeh);
    cudaGetSymbolAddress((void**)&qkv, g_qkv);    cudaGetSymbolAddress((void**)&qc, g_qc);
    cudaGetSymbolAddress((void**)&qp, g_qp);      cudaGetSymbolAddress((void**)&r, g_r);
    cudaGetSymbolAddress((void**)&vt, g_vt);      cudaGetSymbolAddress((void**)&attn, g_attn);
    cudaGetSymbolAddress((void**)&h1, g_h1);      cudaGetSymbolAddress((void**)&h1h, g_h1h);
    cudaGetSymbolAddress((void**)&inner, g_inner);cudaGetSymbolAddress((void**)&tmp, g_tmp);
    cudaGetSymbolAddress((void**)&WqkvT, g_WqkvT);cudaGetSymbolAddress((void**)&WrT, g_WrT);
    cudaGetSymbolAddress((void**)&WoT, g_WoT);    cudaGetSymbolAddress((void**)&WiT, g_WiT);
    cudaGetSymbolAddress((void**)&WoutT, g_WoutT);

    cudaFuncSetAttribute((const void*)hgemm<128,2,4,0,1>,
                         cudaFuncAttributeMaxDynamicSharedMemorySize, HG_SMEM128);
    cudaFuncSetAttribute((const void*)hgemm<128,2,4,0,0>,
                         cudaFuncAttributeMaxDynamicSharedMemorySize, HG_SMEM128);
    cudaFuncSetAttribute((const void*)hgemm<256,2,4,2,1>,
                         cudaFuncAttributeMaxDynamicSharedMemorySize, HG_SMEM256);
    cudaFuncSetAttribute((const void*)hgemm<256,2,4,0,1>,
                         cudaFuncAttributeMaxDynamicSharedMemorySize, HG_SMEM256);
    cudaFuncSetAttribute(flash_k, cudaFuncAttributeMaxDynamicSharedMemorySize, FL_SMEM);

    static cudaStream_t s1 = nullptr, s2 = nullptr, s3 = nullptr;
    static cudaEvent_t  eF = nullptr, e1 = nullptr, e2 = nullptr, e3 = nullptr;
    if (s1 == nullptr) {
        cudaStreamCreateWithFlags(&s1, cudaStreamNonBlocking);
        cudaStreamCreateWithFlags(&s2, cudaStreamNonBlocking);
        cudaStreamCreateWithFlags(&s3, cudaStreamNonBlocking);
        cudaEventCreateWithFlags(&eF, cudaEventDisableTiming);
        cudaEventCreateWithFlags(&e1, cudaEventDisableTiming);
        cudaEventCreateWithFlags(&e2, cudaEventDisableTiming);
        cudaEventCreateWithFlags(&e3, cudaEventDisableTiming);
    }

    const int M = B_ * S_;
    dim3 blk(256);
    const long long Z0 = 0;

    cudaEventRecord(eF, 0);
    cudaStreamWaitEvent(s1, eF, 0);
    cudaStreamWaitEvent(s2, eF, 0);
    cudaStreamWaitEvent(s3, eF, 0);

    f2h_k<<<M * E_ / 1024, blk>>>(x, xh);

    transpose_h16<<<dim3(32, 32), dim3(32, 8), 0, s1>>>(Wq, WqkvT,               E_, NH_);
    transpose_h16<<<dim3(32, 32), dim3(32, 8), 0, s1>>>(Wk, WqkvT + 1024 * 1024, E_, NH_);
    transpose_h16<<<dim3(32, 32), dim3(32, 8), 0, s1>>>(Wv, WqkvT + 2048 * 1024, E_, NH_);
    cudaEventRecord(e1, s1);

    f2h_k<<<B_ * R_ * E_ / 1024, blk, 0, s2>>>(rpe, rpeh);
    transpose_h16<<<dim3(32, 32), dim3(32, 8), 0, s2>>>(Wr, WrT, E_, NH_);
    hgemm<128,2,4,0,1><<<dim3(8,64,1), blk, HG_SMEM128, s2>>>(
        rpeh, WrT, r, nullptr, nullptr, nullptr, nullptr, E_, E_, E_, NH_,
        1, Z0,Z0,Z0,Z0,Z0,Z0, 0, 1.f);
    cudaEventRecord(e2, s2);

    transpose_h16<<<dim3(32, 32),  dim3(32, 8), 0, s3>>>(Wo,   WoT,   NH_, E_);
    transpose_h16<<<dim3(128, 32), dim3(32, 8), 0, s3>>>(Wi,   WiT,   E_, F_);
    transpose_h16<<<dim3(32, 128), dim3(32, 8), 0, s3>>>(Wout, WoutT, F_, E_);
    cudaEventRecord(e3, s3);

    // QKV mega-GEMM with BN=256 (12 x-tiles cover N=3072)
    cudaStreamWaitEvent(0, e1, 0);
    hgemm<256,2,4,2,1><<<dim3(12,32,1), blk, HG_SMEM256>>>(
        xh, WqkvT, qkv, cb, pb, qc, qp, E_, E_, E_, 3*NH_,
        1, Z0,Z0,Z0,Z0,Z0,Z0, 0, 1.f);
    transpose_vh<<<dim3(S_/32, 2, B_*NHEADS), dim3(32,8)>>>(qkv + 2*NH_, vt, S_, 3*NH_);

    cudaStreamWaitEvent(0, e2, 0);
    flash_k<<<dim3(8, B_ * NHEADS), blk, FL_SMEM>>>(qc, qp, qkv + NH_, vt, r, attn, 3*NH_);

    cudaStreamWaitEvent(0, e3, 0);
    hgemm<128,2,4,0,0><<<dim3(8,32,1), blk, HG_SMEM128>>>(
        attn, WoT, tmp, nullptr, nullptr, nullptr, nullptr, NH_, NH_, NH_, E_,
        1, Z0,Z0,Z0,Z0,Z0,Z0, 0, 1.f);
    ln_k<<<M, 256>>>(tmp, x, ln1g, ln1b, h1, h1h);

    // FFN1 with BN=256 (16 x-tiles cover F=4096)
    hgemm<256,2,4,0,1><<<dim3(16,32,1), blk, HG_SMEM256>>>(
        h1h, WiT, inner, bi, nullptr, nullptr, nullptr, E_, E_, E_, F_,
        1, Z0,Z0,Z0,Z0,Z0,Z0, 1, 1.f);
    hgemm<128,2,4,0,0><<<dim3(8,32,1), blk, HG_SMEM128>>>(
        inner, WoutT, tmp, bout, nullptr, nullptr, nullptr, F_, F_, F_, E_,
        1, Z0,Z0,Z0,Z0,Z0,Z0, 0, 1.f);
    ln_k<<<M, 256>>>(tmp, h1, ln2g, ln2b, out, nullptr);
}

// round 14
// speedup vs baseline: 1.0334x; 1.0334x over previous
#include <cuda_runtime.h>
#include <cuda_fp16.h>
#include <math.h>
#include <stdint.h>

#define B_      4
#define S_      1024
#define E_      1024
#define NHEADS  16
#define H_      64
#define NH_     1024
#define F_      4096
#define R_      2048

// ---------------- scratch (static device globals) ----------------
__device__ __half g_xh[4194304];
__device__ __half g_rpeh[8388608];
__device__ __half g_qkv[12582912];     // [B,S,3NH]
__device__ __half g_qc[4194304];
__device__ __half g_qp[4194304];
__device__ __half g_r[8388608];
__device__ __half g_vt[4194304];       // [B,N,H,S]
__device__ __half g_attn[4194304];
__device__ float  g_h1[4194304];
__device__ __half g_h1h[4194304];
__device__ __half g_inner[16777216];
__device__ float  g_tmp[4194304];
__device__ __half g_WqkvT[3145728];
__device__ __half g_WrT[1048576];
__device__ __half g_WoT[1048576];
__device__ __half g_WiT[4194304];
__device__ __half g_WoutT[4194304];

// ---------------- helpers ----------------
__device__ __forceinline__ uint32_t smem_u32(const void* p) {
    uint32_t a;
    asm("{ .reg .u64 t; cvta.to.shared.u64 t, %1; cvt.u32.u64 %0, t; }" : "=r"(a) : "l"(p));
    return a;
}
__device__ __forceinline__ void cpasync16(uint32_t s, const void* g) {
    asm volatile("cp.async.cg.shared.global [%0], [%1], 16;" :: "r"(s), "l"(g));
}
#define CP_COMMIT() asm volatile("cp.async.commit_group;" ::: "memory")
#define CP_WAIT(n)  asm volatile("cp.async.wait_group %0;" :: "n"(n) : "memory")

#define LDM4(r0, r1, r2, r3, a)                                                     \
    asm volatile("ldmatrix.sync.aligned.m8n8.x4.shared.b16 {%0,%1,%2,%3}, [%4];"    \
                 : "=r"(r0), "=r"(r1), "=r"(r2), "=r"(r3) : "r"(a))

#define MMA16816(c, a, b)                                                           \
    asm volatile("mma.sync.aligned.m16n8k16.row.col.f32.f16.f16.f32 "               \
                 "{%0,%1,%2,%3},{%4,%5,%6,%7},{%8,%9},{%0,%1,%2,%3};"               \
                 : "+f"((c)[0]), "+f"((c)[1]), "+f"((c)[2]), "+f"((c)[3])           \
                 : "r"((a)[0]), "r"((a)[1]), "r"((a)[2]), "r"((a)[3]),              \
                   "r"((b)[0]), "r"((b)[1]))

// exp on FMA/ALU pipes; common-mode error cancels in softmax normalization.
__device__ __forceinline__ float fast_exp(float x) {
    float t = fmaxf(x * 1.44269504f, -126.f);
    float fl = floorf(t);
    float f = t - fl;
    float p = fmaf(f, 0.0792345f, 0.2248712f);
    p = fmaf(f, p, 0.6958943f);
    p = fmaf(f, p, 1.0f);
    return __int_as_float(__float_as_int(p) + (((int)fl) << 23));
}

// ---------------- fp16 tensor-core GEMM, K-chunk 64, 3-stage ring ---------------
// EPI 0: store (+bias/relu/scale), OUTH picks half/float.
// EPI 2: QKV epilogue — col<NH_: qc=(v+cb)/8, qp=(v+pb)/8 (half); else store half.
#define LDSG 72
#define HG_SMEM (3 * (128 + 128) * LDSG * 2)
template<int BN, int WRM, int WRN, int EPI, int OUTH>
__global__ __launch_bounds__(256, 2) void hgemm(
    const __half* __restrict__ A, const __half* __restrict__ Bm,
    void* __restrict__ Cv, const float* __restrict__ bias,
    const float* __restrict__ pb, __half* __restrict__ qcp, __half* __restrict__ qpp,
    int K, int lda, int ldb, int ldc, int zdiv,
    long long As1, long long As2, long long Bs1, long long Bs2,
    long long Cs1, long long Cs2, int relu, float scale)
{
    constexpr int BM = 128;
    constexpr int MW = BM / WRM, NW = BN / WRN;
    constexpr int MT = MW / 16, NPAIR = NW / 16, NT = NW / 8;
    extern __shared__ __half hsm[];
    __half* sA = hsm;
    __half* sB = hsm + 3 * BM * LDSG;

    const int bm = blockIdx.y * BM, bn = blockIdx.x * BN;
    {
        int z = blockIdx.z, zq = z / zdiv, zr = z % zdiv;
        A  += zq * As1 + zr * As2;
        Bm += zq * Bs1 + zr * Bs2;
    }
    const int tid = threadIdx.x, lane = tid & 31, wid = tid >> 5;
    const int wm = (wid / WRN) * MW, wn = (wid % WRN) * NW;

    float cf[MT][NT][4];
#pragma unroll
    for (int i = 0; i < MT; i++)
#pragma unroll
        for (int j = 0; j < NT; j++)
#pragma unroll
            for (int e = 0; e < 4; e++) cf[i][j][e] = 0.f;

    auto stage = [&](int c, int sx) {
        __half* dA = sA + sx * BM * LDSG;
        __half* dB = sB + sx * BN * LDSG;
#pragma unroll
        for (int i = 0; i < BM * 8 / 256; i++) {
            int id = tid + i * 256, row = id >> 3, ch = id & 7;
            cpasync16(smem_u32(dA + row * LDSG + ch * 8),
                      A + (long long)(bm + row) * lda + c * 64 + ch * 8);
        }
#pragma unroll
        for (int i = 0; i < BN * 8 / 256; i++) {
            int id = tid + i * 256, row = id >> 3, ch = id & 7;
            cpasync16(smem_u32(dB + row * LDSG + ch * 8),
                      Bm + (long long)(bn + row) * ldb + c * 64 + ch * 8);
        }
        CP_COMMIT();
    };

    const int nkt = K >> 6;
    stage(0, 0);
    stage(1, 1);
    int cbuf = 0, pbuf = 2;
    for (int c = 0; c < nkt; c++) {
        CP_WAIT(1);
        __syncthreads();
        if (c + 2 < nkt) stage(c + 2, pbuf);
        else CP_COMMIT();
        const uint32_t a0 = smem_u32(sA + cbuf * BM * LDSG);
        const uint32_t b0 = smem_u32(sB + cbuf * BN * LDSG);
#pragma unroll
        for (int ks = 0; ks < 4; ks++) {
            uint32_t af[MT][4], bf[NT][2];
#pragma unroll
            for (int mt = 0; mt < MT; mt++) {
                uint32_t ad = a0 + ((wm + mt * 16 + (lane & 15)) * LDSG
                                    + ks * 16 + (lane >> 4) * 8) * 2;
                LDM4(af[mt][0], af[mt][1], af[mt][2], af[mt][3], ad);
            }
#pragma unroll
            for (int p = 0; p < NPAIR; p++) {
                int rn = wn + p * 16 + (lane & 7) + ((lane >> 4) << 3);
                uint32_t bd = b0 + (rn * LDSG + ks * 16 + ((lane >> 3) & 1) * 8) * 2;
                uint32_t r0, r1, r2, r3;
                LDM4(r0, r1, r2, r3, bd);
                bf[2 * p][0] = r0; bf[2 * p][1] = r1;
                bf[2 * p + 1][0] = r2; bf[2 * p + 1][1] = r3;
            }
#pragma unroll
            for (int mt = 0; mt < MT; mt++)
#pragma unroll
                for (int nt = 0; nt < NT; nt++)
                    MMA16816(cf[mt][nt], af[mt], bf[nt]);
        }
        cbuf = cbuf == 2 ? 0 : cbuf + 1;
        pbuf = pbuf == 2 ? 0 : pbuf + 1;
    }

    long long coff;
    {
        int z = blockIdx.z, zq = z / zdiv, zr = z % zdiv;
        coff = zq * Cs1 + zr * Cs2;
    }
#pragma unroll
    for (int mt = 0; mt < MT; mt++) {
#pragma unroll
        for (int nt = 0; nt < NT; nt++) {
            int r = bm + wm + mt * 16 + (lane >> 2);
            int col = bn + wn + nt * 8 + (lane & 3) * 2;
#pragma unroll
            for (int e2 = 0; e2 < 2; e2++) {
                int row = r + 8 * e2;
                float v0 = cf[mt][nt][e2 * 2] * scale;
                float v1 = cf[mt][nt][e2 * 2 + 1] * scale;
                if (EPI == 2) {
                    if (col < NH_) {
                        float c0 = bias[col], c1 = bias[col + 1];
                        float p0 = pb[col],  p1 = pb[col + 1];
                        *(__half2*)(qcp + (long long)row * NH_ + col) =
                            __floats2half2_rn((v0 + c0) * 0.125f, (v1 + c1) * 0.125f);
                        *(__half2*)(qpp + (long long)row * NH_ + col) =
                            __floats2half2_rn((v0 + p0) * 0.125f, (v1 + p1) * 0.125f);
                    } else {
                        __half* Ch = (__half*)Cv;
                        *(__half2*)(Ch + (long long)row * ldc + col) =
                            __floats2half2_rn(v0, v1);
                    }
                } else {
                    if (bias) { v0 += bias[col]; v1 += bias[col + 1]; }
                    if (relu) { v0 = fmaxf(v0, 0.f); v1 = fmaxf(v1, 0.f); }
                    if (OUTH) {
                        __half* Ch = (__half*)Cv + coff;
                        *(__half2*)(Ch + (long long)row * ldc + col) =
                            __floats2half2_rn(v0, v1);
                    } else {
                        float* Cf = (float*)Cv + coff;
                        *(float2*)(Cf + (long long)row * ldc + col) = make_float2(v0, v1);
                    }
                }
            }
        }
    }
}

// ---------------- flash attention: merged content+pos phase, staged K/R/V -------
#define LDQ_  72
#define LDV_  136
#define LDS_S 132
#define LDP_  136
#define FL_SMEM (3*128*LDQ_*2 + 64*LDV_*2 + 256*LDQ_*2 + 128*LDS_S*4 + 128*LDP_*2 + 3*128*4)

__global__ __launch_bounds__(256, 1) void flash_k(
    const __half* __restrict__ qc, const __half* __restrict__ qp,
    const __half* __restrict__ kk, const __half* __restrict__ vt,
    const __half* __restrict__ rr, __half* __restrict__ attn, int kstr)
{
    extern __shared__ char smraw[];
    __half* sQc = (__half*)smraw;
    __half* sQp = sQc + 128 * LDQ_;
    __half* sK  = sQp + 128 * LDQ_;
    __half* sV  = sK  + 128 * LDQ_;
    __half* sR  = sV  + 64 * LDV_;
    float*  sS  = (float*)(sR + 256 * LDQ_);
    __half* sP  = (__half*)(sS + 128 * LDS_S);
    float*  sM  = (float*)(sP + 128 * LDP_);
    float*  sL  = sM + 128;
    float*  sAl = sL + 128;

    const int it = blockIdx.x, z = blockIdx.y;
    const int b = z >> 4, n = z & 15;
    const int i0 = it * 128;
    const int tid = threadIdx.x, lane = tid & 31, wid = tid >> 5;
    const int wm = wid * 16;

    int ntlo0 = (105 - wm + 7) >> 3; if (ntlo0 < 0) ntlo0 = 0;
    int nthi1 = (126 - wm) >> 3;

    const __half* qcb = qc + (long long)b * S_ * NH_ + n * H_;
    const __half* qpb = qp + (long long)b * S_ * NH_ + n * H_;
    const __half* kb  = kk + (long long)b * S_ * kstr + n * H_;
    const __half* vtb = vt + (long long)z * H_ * S_;
    const __half* rb  = rr + (long long)b * R_ * NH_ + n * H_;

    auto stageK = [&](int jt) {
        const int j0 = jt * 128;
        if (jt < 8) {
#pragma unroll
            for (int i = 0; i < 4; i++) {
                int id = tid + i * 256, row = id >> 3, ch = id & 7;
                cpasync16(smem_u32(sK + row * LDQ_ + ch * 8),
                          kb + (long long)(j0 + row) * kstr + ch * 8);
            }
        }
        CP_COMMIT();
    };
    auto stageR = [&](int jt) {
        const int base = S_ + jt * 128 - i0 - 127;
        if (jt < 8) {
#pragma unroll
            for (int i = 0; i < 8; i++) {
                int id = tid + i * 256, row = id >> 3, ch = id & 7;
                int grow = base + row; grow = grow < R_ ? grow : R_ - 1;
                cpasync16(smem_u32(sR + row * LDQ_ + ch * 8),
                          rb + (long long)grow * NH_ + ch * 8);
            }
        }
        CP_COMMIT();
    };
    auto stageV = [&](int jt) {
        const int j0 = jt * 128;
        if (jt < 8) {
#pragma unroll
            for (int i = 0; i < 4; i++) {
                int id = tid + i * 256, row = id >> 4, ch = id & 15;
                cpasync16(smem_u32(sV + row * LDV_ + ch * 8),
                          vtb + (long long)row * S_ + j0 + ch * 8);
            }
        }
        CP_COMMIT();
    };

    // prologue: groups [Q+K0, R0, V0]
#pragma unroll
    for (int i = 0; i < 4; i++) {
        int id = tid + i * 256, row = id >> 3, ch = id & 7;
        cpasync16(smem_u32(sQc + row * LDQ_ + ch * 8),
                  qcb + (long long)(i0 + row) * NH_ + ch * 8);
        cpasync16(smem_u32(sQp + row * LDQ_ + ch * 8),
                  qpb + (long long)(i0 + row) * NH_ + ch * 8);
    }
    stageK(0);
    stageR(0);
    stageV(0);
    if (tid < 128) { sM[tid] = -1e30f; sL[tid] = 0.f; }

    float of[8][4];
#pragma unroll
    for (int nt = 0; nt < 8; nt++)
#pragma unroll
        for (int e = 0; e < 4; e++) of[nt][e] = 0.f;

    const uint32_t aQc = smem_u32(sQc), aQp = smem_u32(sQp);
    const uint32_t aK = smem_u32(sK), aV = smem_u32(sV);
    const uint32_t aR = smem_u32(sR), aP = smem_u32(sP);

    for (int jt = 0; jt < 8; jt++) {
        CP_WAIT(1);              // K(jt) and R(jt) landed (V(jt) may be pending)
        __syncthreads();

        // ---- content scores -> sS (no barrier before pos: rows warp-private) ----
        float cf[16][4];
#pragma unroll
        for (int nt = 0; nt < 16; nt++)
#pragma unroll
            for (int e = 0; e < 4; e++) cf[nt][e] = 0.f;
#pragma unroll
        for (int ks = 0; ks < 4; ks++) {
            uint32_t af[4], bf[16][2];
            LDM4(af[0], af[1], af[2], af[3],
                 aQc + ((wm + (lane & 15)) * LDQ_ + ks * 16 + (lane >> 4) * 8) * 2);
#pragma unroll
            for (int p = 0; p < 8; p++) {
                int rn = p * 16 + (lane & 7) + ((lane >> 4) << 3);
                uint32_t r0, r1, r2, r3;
                LDM4(r0, r1, r2, r3, aK + (rn * LDQ_ + ks * 16 + ((lane >> 3) & 1) * 8) * 2);
                bf[2 * p][0] = r0; bf[2 * p][1] = r1;
                bf[2 * p + 1][0] = r2; bf[2 * p + 1][1] = r3;
            }
#pragma unroll
            for (int nt = 0; nt < 16; nt++) MMA16816(cf[nt], af, bf[nt]);
        }
#pragma unroll
        for (int nt = 0; nt < 16; nt++) {
            int c0 = nt * 8 + (lane & 3) * 2;
#pragma unroll
            for (int e2 = 0; e2 < 2; e2++) {
                int row = wm + (lane >> 2) + 8 * e2;
                *(float2*)&sS[row * LDS_S + c0] = make_float2(cf[nt][e2 * 2], cf[nt][e2 * 2 + 1]);
            }
        }
        __syncwarp();

        // ---- position scores immediately (R resident since last iter) ----
#pragma unroll
        for (int halfg = 0; halfg < 2; halfg++) {
            int g0 = halfg * 128;
            int lo = halfg == 0 ? ntlo0 : 0;
            int hi = halfg == 0 ? 15 : nthi1;
#pragma unroll
            for (int nt = 0; nt < 16; nt++)
#pragma unroll
                for (int e = 0; e < 4; e++) cf[nt][e] = 0.f;
#pragma unroll
            for (int ks = 0; ks < 4; ks++) {
                uint32_t af[4], bf[16][2];
                LDM4(af[0], af[1], af[2], af[3],
                     aQp + ((wm + (lane & 15)) * LDQ_ + ks * 16 + (lane >> 4) * 8) * 2);
#pragma unroll
                for (int p = 0; p < 8; p++) {
                    if (2 * p + 1 < lo || 2 * p > hi) continue;
                    int rn = g0 + p * 16 + (lane & 7) + ((lane >> 4) << 3);
                    uint32_t r0, r1, r2, r3;
                    LDM4(r0, r1, r2, r3, aR + (rn * LDQ_ + ks * 16 + ((lane >> 3) & 1) * 8) * 2);
                    bf[2 * p][0] = r0; bf[2 * p][1] = r1;
                    bf[2 * p + 1][0] = r2; bf[2 * p + 1][1] = r3;
                }
#pragma unroll
                for (int nt = 0; nt < 16; nt++) {
                    if (nt < lo || nt > hi) continue;
                    MMA16816(cf[nt], af, bf[nt]);
                }
            }
#pragma unroll
            for (int nt = 0; nt < 16; nt++) {
                if (nt < lo || nt > hi) continue;
#pragma unroll
                for (int e = 0; e < 4; e++) {
                    int li = wm + (lane >> 2) + 8 * (e >> 1);
                    int g  = g0 + nt * 8 + (lane & 3) * 2 + (e & 1);
                    int lj = g - 127 + li;
                    if (lj >= 0 && lj < 128) sS[li * LDS_S + lj] += cf[nt][e];
                }
            }
            __syncwarp();
        }

        __syncthreads();         // all warps finished reading sK and sR
        stageK(jt + 1);
        stageR(jt + 1);

        // ---- online softmax ----
        {
            int rloc = wm + (lane >> 1), hf = lane & 1;
            float* srow = &sS[rloc * LDS_S + hf * 64];
            float4* srow4 = (float4*)srow;
            float m0 = -1e30f, m1 = -1e30f, m2 = -1e30f, m3 = -1e30f;
#pragma unroll
            for (int c = 0; c < 16; c += 2) {
                float4 a = srow4[c], bq = srow4[c + 1];
                m0 = fmaxf(m0, fmaxf(a.x, a.y));
                m1 = fmaxf(m1, fmaxf(a.z, a.w));
                m2 = fmaxf(m2, fmaxf(bq.x, bq.y));
                m3 = fmaxf(m3, fmaxf(bq.z, bq.w));
            }
            float mx = fmaxf(fmaxf(m0, m1), fmaxf(m2, m3));
            mx = fmaxf(mx, __shfl_xor_sync(0xffffffffu, mx, 1));
            float mold = sM[rloc];
            float mnew = fmaxf(mold, mx);
            float alpha = fast_exp(mold - mnew);
            float s0 = 0.f, s1 = 0.f;
            __half* prow = &sP[rloc * LDP_ + hf * 64];
#pragma unroll
            for (int c = 0; c < 16; c++) {
                float4 a = srow4[c];
                float p0 = fast_exp(a.x - mnew);
                float p1 = fast_exp(a.y - mnew);
                float p2 = fast_exp(a.z - mnew);
                float p3 = fast_exp(a.w - mnew);
                s0 += p0 + p1;
                s1 += p2 + p3;
                *(__half2*)&prow[c * 4]     = __floats2half2_rn(p0, p1);
                *(__half2*)&prow[c * 4 + 2] = __floats2half2_rn(p2, p3);
            }
            float sum = s0 + s1;
            sum += __shfl_xor_sync(0xffffffffu, sum, 1);
            if (hf == 0) {
                sL[rloc] = sL[rloc] * alpha + sum;
                sM[rloc] = mnew;
                sAl[rloc] = alpha;
            }
        }
        __syncwarp();

        CP_WAIT(2);              // V(jt) landed (K+1, R+1 still pending)
        __syncthreads();

        // ---- rescale O, PV mma ----
#pragma unroll
        for (int e2 = 0; e2 < 2; e2++) {
            float al = sAl[wm + (lane >> 2) + 8 * e2];
#pragma unroll
            for (int nt = 0; nt < 8; nt++) {
                of[nt][e2 * 2]     *= al;
                of[nt][e2 * 2 + 1] *= al;
            }
        }
#pragma unroll
        for (int ks = 0; ks < 8; ks++) {
            uint32_t af[4], bfv[8][2];
            LDM4(af[0], af[1], af[2], af[3],
                 aP + ((wm + (lane & 15)) * LDP_ + ks * 16 + (lane >> 4) * 8) * 2);
#pragma unroll
            for (int p = 0; p < 4; p++) {
                int rn = p * 16 + (lane & 7) + ((lane >> 4) << 3);
                uint32_t r0, r1, r2, r3;
                LDM4(r0, r1, r2, r3, aV + (rn * LDV_ + ks * 16 + ((lane >> 3) & 1) * 8) * 2);
                bfv[2 * p][0] = r0; bfv[2 * p][1] = r1;
                bfv[2 * p + 1][0] = r2; bfv[2 * p + 1][1] = r3;
            }
#pragma unroll
            for (int nt = 0; nt < 8; nt++) MMA16816(of[nt], af, bfv[nt]);
        }
        __syncthreads();         // all warps done reading sV
        stageV(jt + 1);
    }

#pragma unroll
    for (int e2 = 0; e2 < 2; e2++) {
        int li = wm + (lane >> 2) + 8 * e2;
        float inv = 1.0f / sL[li];
        long long rowg = (long long)(b * S_ + i0 + li) * NH_ + n * H_;
#pragma unroll
        for (int nt = 0; nt < 8; nt++) {
            int col = nt * 8 + (lane & 3) * 2;
            *(__half2*)(attn + rowg + col) =
                __floats2half2_rn(of[nt][e2 * 2] * inv, of[nt][e2 * 2 + 1] * inv);
        }
    }
}

// ---------------- fp32 -> fp16 copy ----------------
__global__ __launch_bounds__(256) void f2h_k(const float* __restrict__ in,
                                             __half* __restrict__ out)
{
    long long i = (long long)blockIdx.x * 256 + threadIdx.x;
    float4 v = ((const float4*)in)[i];
    ((__half2*)out)[i * 2]     = __floats2half2_rn(v.x, v.y);
    ((__half2*)out)[i * 2 + 1] = __floats2half2_rn(v.z, v.w);
}

// ---------------- fp32 transpose -> fp16 ----------------
__global__ void transpose_h16(const float* __restrict__ in, __half* __restrict__ out,
                              int rows, int cols)
{
    __shared__ float tile[32][33];
    int r0 = blockIdx.y * 32, c0 = blockIdx.x * 32;
    int tx = threadIdx.x, ty = threadIdx.y;
#pragma unroll
    for (int i = 0; i < 4; i++)
        tile[ty + i * 8][tx] = in[(long long)(r0 + ty + i * 8) * cols + c0 + tx];
    __syncthreads();
#pragma unroll
    for (int i = 0; i < 4; i++)
        out[(long long)(c0 + ty + i * 8) * rows + r0 + tx] = __float2half_rn(tile[tx][ty + i * 8]);
}

// ---------------- per-head half transpose ----------------
__global__ void transpose_vh(const __half* __restrict__ in, __half* __restrict__ out,
                             int rows, int instr)
{
    __shared__ __half tile[32][34];
    int z = blockIdx.z, b = z >> 4, n = z & 15;
    const __half* ip = in + (long long)b * rows * instr + n * H_;
    __half* op = out + (long long)z * H_ * rows;
    int r0 = blockIdx.x * 32, h0 = blockIdx.y * 32;
    int tx = threadIdx.x, ty = threadIdx.y;
#pragma unroll
    for (int i = 0; i < 4; i++)
        tile[ty + i * 8][tx] = ip[(long long)(r0 + ty + i * 8) * instr + h0 + tx];
    __syncthreads();
#pragma unroll
    for (int i = 0; i < 4; i++)
        op[(long long)(h0 + ty + i * 8) * rows + r0 + tx] = tile[tx][ty + i * 8];
}

// ---------------- residual + LayerNorm (optional fp16 copy) ---------------------
__global__ __launch_bounds__(256) void ln_k(
    const float* __restrict__ a, const float* __restrict__ res,
    const float* __restrict__ g, const float* __restrict__ bt,
    float* __restrict__ o, __half* __restrict__ oh)
{
    __shared__ float red[16];
    long long row = blockIdx.x;
    int t = threadIdx.x;
    float4 va = *((const float4*)(a + row * 1024) + t);
    float4 vr = *((const float4*)(res + row * 1024) + t);
    float4 x;
    x.x = va.x + vr.x; x.y = va.y + vr.y; x.z = va.z + vr.z; x.w = va.w + vr.w;
    float s  = x.x + x.y + x.z + x.w;
    float q2 = x.x * x.x + x.y * x.y + x.z * x.z + x.w * x.w;
#pragma unroll
    for (int off = 16; off; off >>= 1) {
        s  += __shfl_xor_sync(0xffffffffu, s, off);
        q2 += __shfl_xor_sync(0xffffffffu, q2, off);
    }
    if ((t & 31) == 0) { red[t >> 5] = s; red[8 + (t >> 5)] = q2; }
    __syncthreads();
    if (t == 0) {
        float ss = red[0], qq = red[8];
#pragma unroll
        for (int i = 1; i < 8; i++) { ss += red[i]; qq += red[8 + i]; }
        red[0] = ss; red[8] = qq;
    }
    __syncthreads();
    float mu  = red[0] * (1.f / 1024.f);
    float var = red[8] * (1.f / 1024.f) - mu * mu;
    float rs = rsqrtf(var + 1e-12f);
    float4 gg = *((const float4*)g + t);
    float4 bb = *((const float4*)bt + t);
    float4 y;
    y.x = (x.x - mu) * rs * gg.x + bb.x;
    y.y = (x.y - mu) * rs * gg.y + bb.y;
    y.z = (x.z - mu) * rs * gg.z + bb.z;
    y.w = (x.w - mu) * rs * gg.w + bb.w;
    *((float4*)(o + row * 1024) + t) = y;
    if (oh) {
        __half2* ph = (__half2*)(oh + row * 1024);
        ph[2 * t]     = __floats2half2_rn(y.x, y.y);
        ph[2 * t + 1] = __floats2half2_rn(y.z, y.w);
    }
}

// ---------------- driver --------------------------------------------------------
extern "C" void kernel_launch(void* const* d_in, const int* in_sizes, int n_in,
                              void* d_out, int out_size)
{
    const float* x    = (const float*)d_in[0];
    const float* cb   = (const float*)d_in[1];
    const float* pb   = (const float*)d_in[2];
    const float* rpe  = (const float*)d_in[3];
    const float* Wq   = (const float*)d_in[4];
    const float* Wk   = (const float*)d_in[5];
    const float* Wv   = (const float*)d_in[6];
    const float* Wr   = (const float*)d_in[7];
    const float* Wo   = (const float*)d_in[8];
    const float* ln1g = (const float*)d_in[9];
    const float* ln1b = (const float*)d_in[10];
    const float* Wi   = (const float*)d_in[11];
    const float* bi   = (const float*)d_in[12];
    const float* Wout = (const float*)d_in[13];
    const float* bout = (const float*)d_in[14];
    const float* ln2g = (const float*)d_in[15];
    const float* ln2b = (const float*)d_in[16];
    float* out = (float*)d_out;

    __half *xh,*rpeh,*qkv,*qc,*qp,*r,*vt,*attn,*h1h,*inner;
    __half *WqkvT,*WrT,*WoT,*WiT,*WoutT;
    float *h1,*tmp;
    cudaGetSymbolAddress((void**)&xh, g_xh);      cudaGetSymbolAddress((void**)&rpeh, g_rpeh);
    cudaGetSymbolAddress((void**)&qkv, g_qkv);    cudaGetSymbolAddress((void**)&qc, g_qc);
    cudaGetSymbolAddress((void**)&qp, g_qp);      cudaGetSymbolAddress((void**)&r, g_r);
    cudaGetSymbolAddress((void**)&vt, g_vt);      cudaGetSymbolAddress((void**)&attn, g_attn);
    cudaGetSymbolAddress((void**)&h1, g_h1);      cudaGetSymbolAddress((void**)&h1h, g_h1h);
    cudaGetSymbolAddress((void**)&inner, g_inner);cudaGetSymbolAddress((void**)&tmp, g_tmp);
    cudaGetSymbolAddress((void**)&WqkvT, g_WqkvT);cudaGetSymbolAddress((void**)&WrT, g_WrT);
    cudaGetSymbolAddress((void**)&WoT, g_WoT);    cudaGetSymbolAddress((void**)&WiT, g_WiT);
    cudaGetSymbolAddress((void**)&WoutT, g_WoutT);

    cudaFuncSetAttribute((const void*)hgemm<128,2,4,0,1>,
                         cudaFuncAttributeMaxDynamicSharedMemorySize, HG_SMEM);
    cudaFuncSetAttribute((const void*)hgemm<128,2,4,0,0>,
                         cudaFuncAttributeMaxDynamicSharedMemorySize, HG_SMEM);
    cudaFuncSetAttribute((const void*)hgemm<128,2,4,2,1>,
                         cudaFuncAttributeMaxDynamicSharedMemorySize, HG_SMEM);
    cudaFuncSetAttribute(flash_k, cudaFuncAttributeMaxDynamicSharedMemorySize, FL_SMEM);

    static cudaStream_t s1 = nullptr, s2 = nullptr, s3 = nullptr;
    static cudaEvent_t  eF = nullptr, e1 = nullptr, e2 = nullptr, e3 = nullptr;
    if (s1 == nullptr) {
        cudaStreamCreateWithFlags(&s1, cudaStreamNonBlocking);
        cudaStreamCreateWithFlags(&s2, cudaStreamNonBlocking);
        cudaStreamCreateWithFlags(&s3, cudaStreamNonBlocking);
        cudaEventCreateWithFlags(&eF, cudaEventDisableTiming);
        cudaEventCreateWithFlags(&e1, cudaEventDisableTiming);
        cudaEventCreateWithFlags(&e2, cudaEventDisableTiming);
        cudaEventCreateWithFlags(&e3, cudaEventDisableTiming);
    }

    const int M = B_ * S_;
    dim3 blk(256);
    const long long Z0 = 0;

    cudaEventRecord(eF, 0);
    cudaStreamWaitEvent(s1, eF, 0);
    cudaStreamWaitEvent(s2, eF, 0);
    cudaStreamWaitEvent(s3, eF, 0);

    f2h_k<<<M * E_ / 1024, blk>>>(x, xh);

    transpose_h16<<<dim3(32, 32), dim3(32, 8), 0, s1>>>(Wq, WqkvT,               E_, NH_);
    transpose_h16<<<dim3(32, 32), dim3(32, 8), 0, s1>>>(Wk, WqkvT + 1024 * 1024, E_, NH_);
    transpose_h16<<<dim3(32, 32), dim3(32, 8), 0, s1>>>(Wv, WqkvT + 2048 * 1024, E_, NH_);
    cudaEventRecord(e1, s1);

    f2h_k<<<B_ * R_ * E_ / 1024, blk, 0, s2>>>(rpe, rpeh);
    transpose_h16<<<dim3(32, 32), dim3(32, 8), 0, s2>>>(Wr, WrT, E_, NH_);
    hgemm<128,2,4,0,1><<<dim3(8,64,1), blk, HG_SMEM, s2>>>(
        rpeh, WrT, r, nullptr, nullptr, nullptr, nullptr, E_, E_, E_, NH_,
        1, Z0,Z0,Z0,Z0,Z0,Z0, 0, 1.f);
    cudaEventRecord(e2, s2);

    transpose_h16<<<dim3(32, 32),  dim3(32, 8), 0, s3>>>(Wo,   WoT,   NH_, E_);
    transpose_h16<<<dim3(128, 32), dim3(32, 8), 0, s3>>>(Wi,   WiT,   E_, F_);
    transpose_h16<<<dim3(32, 128), dim3(32, 8), 0, s3>>>(Wout, WoutT, F_, E_);
    cudaEventRecord(e3, s3);

    cudaStreamWaitEvent(0, e1, 0);
    hgemm<128,2,4,2,1><<<dim3(24,32,1), blk, HG_SMEM>>>(
        xh, WqkvT, qkv, cb, pb, qc, qp, E_, E_, E_, 3*NH_,
        1, Z0,Z0,Z0,Z0,Z0,Z0, 0, 1.f);
    transpose_vh<<<dim3(S_/32, 2, B_*NHEADS), dim3(32,8)>>>(qkv + 2*NH_, vt, S_, 3*NH_);

    cudaStreamWaitEvent(0, e2, 0);
    flash_k<<<dim3(8, B_ * NHEADS), blk, FL_SMEM>>>(qc, qp, qkv + NH_, vt, r, attn, 3*NH_);

    cudaStreamWaitEvent(0, e3, 0);
    hgemm<128,2,4,0,0><<<dim3(8,32,1), blk, HG_SMEM>>>(
        attn, WoT, tmp, nullptr, nullptr, nullptr, nullptr, NH_, NH_, NH_, E_,
        1, Z0,Z0,Z0,Z0,Z0,Z0, 0, 1.f);
    ln_k<<<M, 256>>>(tmp, x, ln1g, ln1b, h1, h1h);

    hgemm<128,2,4,0,1><<<dim3(32,32,1), blk, HG_SMEM>>>(
        h1h, WiT, inner, bi, nullptr, nullptr, nullptr, E_, E_, E_, F_,
        1, Z0,Z0,Z0,Z0,Z0,Z0, 1, 1.f);
    hgemm<128,2,4,0,0><<<dim3(8,32,1), blk, HG_SMEM>>>(
        inner, WoutT, tmp, bout, nullptr, nullptr, nullptr, F_, F_, F_, E_,
        1, Z0,Z0,Z0,Z0,Z0,Z0, 0, 1.f);
    ln_k<<<M, 256>>>(tmp, h1, ln2g, ln2b, out, nullptr);
}

// round 15
// speedup vs baseline: 1.0630x; 1.0286x over previous
#include <cuda_runtime.h>
#include <cuda_fp16.h>
#include <math.h>
#include <stdint.h>

#define B_      4
#define S_      1024
#define E_      1024
#define NHEADS  16
#define H_      64
#define NH_     1024
#define F_      4096
#define R_      2048

// ---------------- scratch (static device globals) ----------------
__device__ __half g_xh[4194304];
__device__ __half g_rpeh[8388608];
__device__ __half g_qkv[12582912];     // [B,S,3NH]
__device__ __half g_qc[4194304];
__device__ __half g_qp[4194304];
__device__ __half g_r[8388608];
__device__ __half g_vt[4194304];       // [B,N,H,S]
__device__ __half g_attn[4194304];
__device__ float  g_opart[8388608];    // [2][z*S + i][H] unnormalized O halves
__device__ float  g_ml[262144];        // [2][row][m,l]
__device__ float  g_h1[4194304];
__device__ __half g_h1h[4194304];
__device__ __half g_inner[16777216];
__device__ float  g_tmp[4194304];
__device__ __half g_WqkvT[3145728];
__device__ __half g_WrT[1048576];
__device__ __half g_WoT[1048576];
__device__ __half g_WiT[4194304];
__device__ __half g_WoutT[4194304];

// ---------------- helpers ----------------
__device__ __forceinline__ uint32_t smem_u32(const void* p) {
    uint32_t a;
    asm("{ .reg .u64 t; cvta.to.shared.u64 t, %1; cvt.u32.u64 %0, t; }" : "=r"(a) : "l"(p));
    return a;
}
__device__ __forceinline__ void cpasync16(uint32_t s, const void* g) {
    asm volatile("cp.async.cg.shared.global [%0], [%1], 16;" :: "r"(s), "l"(g));
}
#define CP_COMMIT() asm volatile("cp.async.commit_group;" ::: "memory")
#define CP_WAIT(n)  asm volatile("cp.async.wait_group %0;" :: "n"(n) : "memory")

#define LDM4(r0, r1, r2, r3, a)                                                     \
    asm volatile("ldmatrix.sync.aligned.m8n8.x4.shared.b16 {%0,%1,%2,%3}, [%4];"    \
                 : "=r"(r0), "=r"(r1), "=r"(r2), "=r"(r3) : "r"(a))

#define MMA16816(c, a, b)                                                           \
    asm volatile("mma.sync.aligned.m16n8k16.row.col.f32.f16.f16.f32 "               \
                 "{%0,%1,%2,%3},{%4,%5,%6,%7},{%8,%9},{%0,%1,%2,%3};"               \
                 : "+f"((c)[0]), "+f"((c)[1]), "+f"((c)[2]), "+f"((c)[3])           \
                 : "r"((a)[0]), "r"((a)[1]), "r"((a)[2]), "r"((a)[3]),              \
                   "r"((b)[0]), "r"((b)[1]))

// exp on FMA/ALU pipes; common-mode error cancels in softmax normalization.
__device__ __forceinline__ float fast_exp(float x) {
    float t = fmaxf(x * 1.44269504f, -126.f);
    float fl = floorf(t);
    float f = t - fl;
    float p = fmaf(f, 0.0792345f, 0.2248712f);
    p = fmaf(f, p, 0.6958943f);
    p = fmaf(f, p, 1.0f);
    return __int_as_float(__float_as_int(p) + (((int)fl) << 23));
}

// ---------------- fp16 tensor-core GEMM, K-chunk 64, 3-stage ring ---------------
// EPI 0: store (+bias/relu/scale), OUTH picks half/float.
// EPI 2: QKV epilogue — col<NH_: qc=(v+cb)/8, qp=(v+pb)/8 (half); else store half.
#define LDSG 72
#define HG_SMEM (3 * (128 + 128) * LDSG * 2)
template<int BN, int WRM, int WRN, int EPI, int OUTH>
__global__ __launch_bounds__(256, 2) void hgemm(
    const __half* __restrict__ A, const __half* __restrict__ Bm,
    void* __restrict__ Cv, const float* __restrict__ bias,
    const float* __restrict__ pb, __half* __restrict__ qcp, __half* __restrict__ qpp,
    int K, int lda, int ldb, int ldc, int zdiv,
    long long As1, long long As2, long long Bs1, long long Bs2,
    long long Cs1, long long Cs2, int relu, float scale)
{
    constexpr int BM = 128;
    constexpr int MW = BM / WRM, NW = BN / WRN;
    constexpr int MT = MW / 16, NPAIR = NW / 16, NT = NW / 8;
    extern __shared__ __half hsm[];
    __half* sA = hsm;
    __half* sB = hsm + 3 * BM * LDSG;

    const int bm = blockIdx.y * BM, bn = blockIdx.x * BN;
    {
        int z = blockIdx.z, zq = z / zdiv, zr = z % zdiv;
        A  += zq * As1 + zr * As2;
        Bm += zq * Bs1 + zr * Bs2;
    }
    const int tid = threadIdx.x, lane = tid & 31, wid = tid >> 5;
    const int wm = (wid / WRN) * MW, wn = (wid % WRN) * NW;

    float cf[MT][NT][4];
#pragma unroll
    for (int i = 0; i < MT; i++)
#pragma unroll
        for (int j = 0; j < NT; j++)
#pragma unroll
            for (int e = 0; e < 4; e++) cf[i][j][e] = 0.f;

    auto stage = [&](int c, int sx) {
        __half* dA = sA + sx * BM * LDSG;
        __half* dB = sB + sx * BN * LDSG;
#pragma unroll
        for (int i = 0; i < BM * 8 / 256; i++) {
            int id = tid + i * 256, row = id >> 3, ch = id & 7;
            cpasync16(smem_u32(dA + row * LDSG + ch * 8),
                      A + (long long)(bm + row) * lda + c * 64 + ch * 8);
        }
#pragma unroll
        for (int i = 0; i < BN * 8 / 256; i++) {
            int id = tid + i * 256, row = id >> 3, ch = id & 7;
            cpasync16(smem_u32(dB + row * LDSG + ch * 8),
                      Bm + (long long)(bn + row) * ldb + c * 64 + ch * 8);
        }
        CP_COMMIT();
    };

    const int nkt = K >> 6;
    stage(0, 0);
    stage(1, 1);
    int cbuf = 0, pbuf = 2;
    for (int c = 0; c < nkt; c++) {
        CP_WAIT(1);
        __syncthreads();
        if (c + 2 < nkt) stage(c + 2, pbuf);
        else CP_COMMIT();
        const uint32_t a0 = smem_u32(sA + cbuf * BM * LDSG);
        const uint32_t b0 = smem_u32(sB + cbuf * BN * LDSG);
#pragma unroll
        for (int ks = 0; ks < 4; ks++) {
            uint32_t af[MT][4], bf[NT][2];
#pragma unroll
            for (int mt = 0; mt < MT; mt++) {
                uint32_t ad = a0 + ((wm + mt * 16 + (lane & 15)) * LDSG
                                    + ks * 16 + (lane >> 4) * 8) * 2;
                LDM4(af[mt][0], af[mt][1], af[mt][2], af[mt][3], ad);
            }
#pragma unroll
            for (int p = 0; p < NPAIR; p++) {
                int rn = wn + p * 16 + (lane & 7) + ((lane >> 4) << 3);
                uint32_t bd = b0 + (rn * LDSG + ks * 16 + ((lane >> 3) & 1) * 8) * 2;
                uint32_t r0, r1, r2, r3;
                LDM4(r0, r1, r2, r3, bd);
                bf[2 * p][0] = r0; bf[2 * p][1] = r1;
                bf[2 * p + 1][0] = r2; bf[2 * p + 1][1] = r3;
            }
#pragma unroll
            for (int mt = 0; mt < MT; mt++)
#pragma unroll
                for (int nt = 0; nt < NT; nt++)
                    MMA16816(cf[mt][nt], af[mt], bf[nt]);
        }
        cbuf = cbuf == 2 ? 0 : cbuf + 1;
        pbuf = pbuf == 2 ? 0 : pbuf + 1;
    }

    long long coff;
    {
        int z = blockIdx.z, zq = z / zdiv, zr = z % zdiv;
        coff = zq * Cs1 + zr * Cs2;
    }
#pragma unroll
    for (int mt = 0; mt < MT; mt++) {
#pragma unroll
        for (int nt = 0; nt < NT; nt++) {
            int r = bm + wm + mt * 16 + (lane >> 2);
            int col = bn + wn + nt * 8 + (lane & 3) * 2;
#pragma unroll
            for (int e2 = 0; e2 < 2; e2++) {
                int row = r + 8 * e2;
                float v0 = cf[mt][nt][e2 * 2] * scale;
                float v1 = cf[mt][nt][e2 * 2 + 1] * scale;
                if (EPI == 2) {
                    if (col < NH_) {
                        float c0 = bias[col], c1 = bias[col + 1];
                        float p0 = pb[col],  p1 = pb[col + 1];
                        *(__half2*)(qcp + (long long)row * NH_ + col) =
                            __floats2half2_rn((v0 + c0) * 0.125f, (v1 + c1) * 0.125f);
                        *(__half2*)(qpp + (long long)row * NH_ + col) =
                            __floats2half2_rn((v0 + p0) * 0.125f, (v1 + p1) * 0.125f);
                    } else {
                        __half* Ch = (__half*)Cv;
                        *(__half2*)(Ch + (long long)row * ldc + col) =
                            __floats2half2_rn(v0, v1);
                    }
                } else {
                    if (bias) { v0 += bias[col]; v1 += bias[col + 1]; }
                    if (relu) { v0 = fmaxf(v0, 0.f); v1 = fmaxf(v1, 0.f); }
                    if (OUTH) {
                        __half* Ch = (__half*)Cv + coff;
                        *(__half2*)(Ch + (long long)row * ldc + col) =
                            __floats2half2_rn(v0, v1);
                    } else {
                        float* Cf = (float*)Cv + coff;
                        *(float2*)(Cf + (long long)row * ldc + col) = make_float2(v0, v1);
                    }
                }
            }
        }
    }
}

// ---------------- flash attention, split-KV halves (R11 loop structure) ---------
#define LDQ_  72
#define LDV_  136
#define LDS_S 132
#define LDP_  136
#define FL_SMEM (3*128*LDQ_*2 + 64*LDV_*2 + 256*LDQ_*2 + 128*LDS_S*4 + 128*LDP_*2 + 3*128*4)

__global__ __launch_bounds__(256, 1) void flash_k(
    const __half* __restrict__ qc, const __half* __restrict__ qp,
    const __half* __restrict__ kk, const __half* __restrict__ vt,
    const __half* __restrict__ rr, float* __restrict__ opart,
    float* __restrict__ ml, int kstr)
{
    extern __shared__ char smraw[];
    __half* sQc = (__half*)smraw;
    __half* sQp = sQc + 128 * LDQ_;
    __half* sK  = sQp + 128 * LDQ_;
    __half* sV  = sK  + 128 * LDQ_;
    __half* sR  = sV  + 64 * LDV_;
    float*  sS  = (float*)(sR + 256 * LDQ_);
    __half* sP  = (__half*)(sS + 128 * LDS_S);
    float*  sM  = (float*)(sP + 128 * LDP_);
    float*  sL  = sM + 128;
    float*  sAl = sL + 128;

    const int it = blockIdx.x, z = blockIdx.y, hfk = blockIdx.z;
    const int b = z >> 4, n = z & 15;
    const int i0 = it * 128;
    const int jbeg = hfk * 4, jend = jbeg + 4;
    const int tid = threadIdx.x, lane = tid & 31, wid = tid >> 5;
    const int wm = wid * 16;

    int ntlo0 = (105 - wm + 7) >> 3; if (ntlo0 < 0) ntlo0 = 0;
    int nthi1 = (126 - wm) >> 3;

    const __half* qcb = qc + (long long)b * S_ * NH_ + n * H_;
    const __half* qpb = qp + (long long)b * S_ * NH_ + n * H_;
    const __half* kb  = kk + (long long)b * S_ * kstr + n * H_;
    const __half* vtb = vt + (long long)z * H_ * S_;
    const __half* rb  = rr + (long long)b * R_ * NH_ + n * H_;

    auto stageK = [&](int jt) {
        const int j0 = jt * 128;
        if (jt < jend) {
#pragma unroll
            for (int i = 0; i < 4; i++) {
                int id = tid + i * 256, row = id >> 3, ch = id & 7;
                cpasync16(smem_u32(sK + row * LDQ_ + ch * 8),
                          kb + (long long)(j0 + row) * kstr + ch * 8);
            }
        }
        CP_COMMIT();
    };
    auto stageR = [&](int jt) {
        const int base = S_ + jt * 128 - i0 - 127;
        if (jt < jend) {
#pragma unroll
            for (int i = 0; i < 8; i++) {
                int id = tid + i * 256, row = id >> 3, ch = id & 7;
                int grow = base + row; grow = grow < R_ ? grow : R_ - 1;
                cpasync16(smem_u32(sR + row * LDQ_ + ch * 8),
                          rb + (long long)grow * NH_ + ch * 8);
            }
        }
        CP_COMMIT();
    };
    auto stageV = [&](int jt) {
        const int j0 = jt * 128;
        if (jt < jend) {
#pragma unroll
            for (int i = 0; i < 4; i++) {
                int id = tid + i * 256, row = id >> 4, ch = id & 15;
                cpasync16(smem_u32(sV + row * LDV_ + ch * 8),
                          vtb + (long long)row * S_ + j0 + ch * 8);
            }
        }
        CP_COMMIT();
    };

    // prologue: groups [Q+K, R, V] for jbeg
#pragma unroll
    for (int i = 0; i < 4; i++) {
        int id = tid + i * 256, row = id >> 3, ch = id & 7;
        cpasync16(smem_u32(sQc + row * LDQ_ + ch * 8),
                  qcb + (long long)(i0 + row) * NH_ + ch * 8);
        cpasync16(smem_u32(sQp + row * LDQ_ + ch * 8),
                  qpb + (long long)(i0 + row) * NH_ + ch * 8);
    }
    stageK(jbeg);
    stageR(jbeg);
    stageV(jbeg);
    if (tid < 128) { sM[tid] = -1e30f; sL[tid] = 0.f; }

    float of[8][4];
#pragma unroll
    for (int nt = 0; nt < 8; nt++)
#pragma unroll
        for (int e = 0; e < 4; e++) of[nt][e] = 0.f;

    const uint32_t aQc = smem_u32(sQc), aQp = smem_u32(sQp);
    const uint32_t aK = smem_u32(sK), aV = smem_u32(sV);
    const uint32_t aR = smem_u32(sR), aP = smem_u32(sP);

    for (int jt = jbeg; jt < jend; jt++) {
        CP_WAIT(2);
        __syncthreads();

        // ---- content scores -> sS ----
        float cf[16][4];
#pragma unroll
        for (int nt = 0; nt < 16; nt++)
#pragma unroll
            for (int e = 0; e < 4; e++) cf[nt][e] = 0.f;
#pragma unroll
        for (int ks = 0; ks < 4; ks++) {
            uint32_t af[4], bf[16][2];
            LDM4(af[0], af[1], af[2], af[3],
                 aQc + ((wm + (lane & 15)) * LDQ_ + ks * 16 + (lane >> 4) * 8) * 2);
#pragma unroll
            for (int p = 0; p < 8; p++) {
                int rn = p * 16 + (lane & 7) + ((lane >> 4) << 3);
                uint32_t r0, r1, r2, r3;
                LDM4(r0, r1, r2, r3, aK + (rn * LDQ_ + ks * 16 + ((lane >> 3) & 1) * 8) * 2);
                bf[2 * p][0] = r0; bf[2 * p][1] = r1;
                bf[2 * p + 1][0] = r2; bf[2 * p + 1][1] = r3;
            }
#pragma unroll
            for (int nt = 0; nt < 16; nt++) MMA16816(cf[nt], af, bf[nt]);
        }
#pragma unroll
        for (int nt = 0; nt < 16; nt++) {
            int c0 = nt * 8 + (lane & 3) * 2;
#pragma unroll
            for (int e2 = 0; e2 < 2; e2++) {
                int row = wm + (lane >> 2) + 8 * e2;
                *(float2*)&sS[row * LDS_S + c0] = make_float2(cf[nt][e2 * 2], cf[nt][e2 * 2 + 1]);
            }
        }

        CP_WAIT(1);
        __syncthreads();
        stageK(jt + 1);

        // ---- position scores, band tiles only ----
#pragma unroll
        for (int halfg = 0; halfg < 2; halfg++) {
            int g0 = halfg * 128;
            int lo = halfg == 0 ? ntlo0 : 0;
            int hi = halfg == 0 ? 15 : nthi1;
#pragma unroll
            for (int nt = 0; nt < 16; nt++)
#pragma unroll
                for (int e = 0; e < 4; e++) cf[nt][e] = 0.f;
#pragma unroll
            for (int ks = 0; ks < 4; ks++) {
                uint32_t af[4], bf[16][2];
                LDM4(af[0], af[1], af[2], af[3],
                     aQp + ((wm + (lane & 15)) * LDQ_ + ks * 16 + (lane >> 4) * 8) * 2);
#pragma unroll
                for (int p = 0; p < 8; p++) {
                    if (2 * p + 1 < lo || 2 * p > hi) continue;
                    int rn = g0 + p * 16 + (lane & 7) + ((lane >> 4) << 3);
                    uint32_t r0, r1, r2, r3;
                    LDM4(r0, r1, r2, r3, aR + (rn * LDQ_ + ks * 16 + ((lane >> 3) & 1) * 8) * 2);
                    bf[2 * p][0] = r0; bf[2 * p][1] = r1;
                    bf[2 * p + 1][0] = r2; bf[2 * p + 1][1] = r3;
                }
#pragma unroll
                for (int nt = 0; nt < 16; nt++) {
                    if (nt < lo || nt > hi) continue;
                    MMA16816(cf[nt], af, bf[nt]);
                }
            }
#pragma unroll
            for (int nt = 0; nt < 16; nt++) {
                if (nt < lo || nt > hi) continue;
#pragma unroll
                for (int e = 0; e < 4; e++) {
                    int li = wm + (lane >> 2) + 8 * (e >> 1);
                    int g  = g0 + nt * 8 + (lane & 3) * 2 + (e & 1);
                    int lj = g - 127 + li;
                    if (lj >= 0 && lj < 128) sS[li * LDS_S + lj] += cf[nt][e];
                }
            }
            __syncwarp();
        }

        CP_WAIT(1);
        __syncthreads();
        stageR(jt + 1);

        // ---- online softmax ----
        {
            int rloc = wm + (lane >> 1), hf = lane & 1;
            float* srow = &sS[rloc * LDS_S + hf * 64];
            float4* srow4 = (float4*)srow;
            float m0 = -1e30f, m1 = -1e30f, m2 = -1e30f, m3 = -1e30f;
#pragma unroll
            for (int c = 0; c < 16; c += 2) {
                float4 a = srow4[c], bq = srow4[c + 1];
                m0 = fmaxf(m0, fmaxf(a.x, a.y));
                m1 = fmaxf(m1, fmaxf(a.z, a.w));
                m2 = fmaxf(m2, fmaxf(bq.x, bq.y));
                m3 = fmaxf(m3, fmaxf(bq.z, bq.w));
            }
            float mx = fmaxf(fmaxf(m0, m1), fmaxf(m2, m3));
            mx = fmaxf(mx, __shfl_xor_sync(0xffffffffu, mx, 1));
            float mold = sM[rloc];
            float mnew = fmaxf(mold, mx);
            float alpha = fast_exp(mold - mnew);
            float s0 = 0.f, s1 = 0.f;
            __half* prow = &sP[rloc * LDP_ + hf * 64];
#pragma unroll
            for (int c = 0; c < 16; c++) {
                float4 a = srow4[c];
                float p0 = fast_exp(a.x - mnew);
                float p1 = fast_exp(a.y - mnew);
                float p2 = fast_exp(a.z - mnew);
                float p3 = fast_exp(a.w - mnew);
                s0 += p0 + p1;
                s1 += p2 + p3;
                *(__half2*)&prow[c * 4]     = __floats2half2_rn(p0, p1);
                *(__half2*)&prow[c * 4 + 2] = __floats2half2_rn(p2, p3);
            }
            float sum = s0 + s1;
            sum += __shfl_xor_sync(0xffffffffu, sum, 1);
            if (hf == 0) {
                sL[rloc] = sL[rloc] * alpha + sum;
                sM[rloc] = mnew;
                sAl[rloc] = alpha;
            }
        }
        __syncwarp();

        // ---- rescale O, PV mma ----
#pragma unroll
        for (int e2 = 0; e2 < 2; e2++) {
            float al = sAl[wm + (lane >> 2) + 8 * e2];
#pragma unroll
            for (int nt = 0; nt < 8; nt++) {
                of[nt][e2 * 2]     *= al;
                of[nt][e2 * 2 + 1] *= al;
            }
        }
#pragma unroll
        for (int ks = 0; ks < 8; ks++) {
            uint32_t af[4], bfv[8][2];
            LDM4(af[0], af[1], af[2], af[3],
                 aP + ((wm + (lane & 15)) * LDP_ + ks * 16 + (lane >> 4) * 8) * 2);
#pragma unroll
            for (int p = 0; p < 4; p++) {
                int rn = p * 16 + (lane & 7) + ((lane >> 4) << 3);
                uint32_t r0, r1, r2, r3;
                LDM4(r0, r1, r2, r3, aV + (rn * LDV_ + ks * 16 + ((lane >> 3) & 1) * 8) * 2);
                bfv[2 * p][0] = r0; bfv[2 * p][1] = r1;
                bfv[2 * p + 1][0] = r2; bfv[2 * p + 1][1] = r3;
            }
#pragma unroll
            for (int nt = 0; nt < 8; nt++) MMA16816(of[nt], af, bfv[nt]);
        }
        __syncthreads();
        stageV(jt + 1);
    }

    // ---- epilogue: unnormalized O + (m,l) stats for this half ----
    long long hoff = (long long)hfk * 4194304;
#pragma unroll
    for (int e2 = 0; e2 < 2; e2++) {
        int li = wm + (lane >> 2) + 8 * e2;
        long long rowg = (long long)z * S_ + i0 + li;
#pragma unroll
        for (int nt = 0; nt < 8; nt++) {
            int col = nt * 8 + (lane & 3) * 2;
            *(float2*)(opart + hoff + rowg * H_ + col) =
                make_float2(of[nt][e2 * 2], of[nt][e2 * 2 + 1]);
        }
        if ((lane & 3) == 0) {
            ml[(long long)hfk * 131072 + rowg * 2]     = sM[li];
            ml[(long long)hfk * 131072 + rowg * 2 + 1] = sL[li];
        }
    }
}

// ---------------- split-KV combine: merge two halves -> attn fp16 ---------------
__global__ __launch_bounds__(256) void combine_k(
    const float* __restrict__ opart, const float* __restrict__ ml,
    __half* __restrict__ attn)
{
    int row = blockIdx.x * 8 + (threadIdx.x >> 5);   // z*S + i, 0..65535
    int lane = threadIdx.x & 31;
    int z = row >> 10, i = row & 1023;
    int b = z >> 4, n = z & 15;
    float m1 = ml[row * 2],          l1 = ml[row * 2 + 1];
    float m2 = ml[131072 + row * 2], l2 = ml[131072 + row * 2 + 1];
    float m = fmaxf(m1, m2);
    float a1 = fast_exp(m1 - m), a2 = fast_exp(m2 - m);
    float inv = 1.0f / fmaf(a1, l1, a2 * l2);
    float2 v1 = *(const float2*)(opart + (long long)row * H_ + lane * 2);
    float2 v2 = *(const float2*)(opart + 4194304 + (long long)row * H_ + lane * 2);
    float o0 = fmaf(a1, v1.x, a2 * v2.x) * inv;
    float o1 = fmaf(a1, v1.y, a2 * v2.y) * inv;
    *(__half2*)(attn + (long long)(b * S_ + i) * NH_ + n * H_ + lane * 2) =
        __floats2half2_rn(o0, o1);
}

// ---------------- fp32 -> fp16 copy ----------------
__global__ __launch_bounds__(256) void f2h_k(const float* __restrict__ in,
                                             __half* __restrict__ out)
{
    long long i = (long long)blockIdx.x * 256 + threadIdx.x;
    float4 v = ((const float4*)in)[i];
    ((__half2*)out)[i * 2]     = __floats2half2_rn(v.x, v.y);
    ((__half2*)out)[i * 2 + 1] = __floats2half2_rn(v.z, v.w);
}

// ---------------- fp32 transpose -> fp16 ----------------
__global__ void transpose_h16(const float* __restrict__ in, __half* __restrict__ out,
                              int rows, int cols)
{
    __shared__ float tile[32][33];
    int r0 = blockIdx.y * 32, c0 = blockIdx.x * 32;
    int tx = threadIdx.x, ty = threadIdx.y;
#pragma unroll
    for (int i = 0; i < 4; i++)
        tile[ty + i * 8][tx] = in[(long long)(r0 + ty + i * 8) * cols + c0 + tx];
    __syncthreads();
#pragma unroll
    for (int i = 0; i < 4; i++)
        out[(long long)(c0 + ty + i * 8) * rows + r0 + tx] = __float2half_rn(tile[tx][ty + i * 8]);
}

// ---------------- per-head half transpose ----------------
__global__ void transpose_vh(const __half* __restrict__ in, __half* __restrict__ out,
                             int rows, int instr)
{
    __shared__ __half tile[32][34];
    int z = blockIdx.z, b = z >> 4, n = z & 15;
    const __half* ip = in + (long long)b * rows * instr + n * H_;
    __half* op = out + (long long)z * H_ * rows;
    int r0 = blockIdx.x * 32, h0 = blockIdx.y * 32;
    int tx = threadIdx.x, ty = threadIdx.y;
#pragma unroll
    for (int i = 0; i < 4; i++)
        tile[ty + i * 8][tx] = ip[(long long)(r0 + ty + i * 8) * instr + h0 + tx];
    __syncthreads();
#pragma unroll
    for (int i = 0; i < 4; i++)
        op[(long long)(h0 + ty + i * 8) * rows + r0 + tx] = tile[tx][ty + i * 8];
}

// ---------------- residual + LayerNorm (optional fp16 copy) ---------------------
__global__ __launch_bounds__(256) void ln_k(
    const float* __restrict__ a, const float* __restrict__ res,
    const float* __restrict__ g, const float* __restrict__ bt,
    float* __restrict__ o, __half* __restrict__ oh)
{
    __shared__ float red[16];
    long long row = blockIdx.x;
    int t = threadIdx.x;
    float4 va = *((const float4*)(a + row * 1024) + t);
    float4 vr = *((const float4*)(res + row * 1024) + t);
    float4 x;
    x.x = va.x + vr.x; x.y = va.y + vr.y; x.z = va.z + vr.z; x.w = va.w + vr.w;
    float s  = x.x + x.y + x.z + x.w;
    float q2 = x.x * x.x + x.y * x.y + x.z * x.z + x.w * x.w;
#pragma unroll
    for (int off = 16; off; off >>= 1) {
        s  += __shfl_xor_sync(0xffffffffu, s, off);
        q2 += __shfl_xor_sync(0xffffffffu, q2, off);
    }
    if ((t & 31) == 0) { red[t >> 5] = s; red[8 + (t >> 5)] = q2; }
    __syncthreads();
    if (t == 0) {
        float ss = red[0], qq = red[8];
#pragma unroll
        for (int i = 1; i < 8; i++) { ss += red[i]; qq += red[8 + i]; }
        red[0] = ss; red[8] = qq;
    }
    __syncthreads();
    float mu  = red[0] * (1.f / 1024.f);
    float var = red[8] * (1.f / 1024.f) - mu * mu;
    float rs = rsqrtf(var + 1e-12f);
    float4 gg = *((const float4*)g + t);
    float4 bb = *((const float4*)bt + t);
    float4 y;
    y.x = (x.x - mu) * rs * gg.x + bb.x;
    y.y = (x.y - mu) * rs * gg.y + bb.y;
    y.z = (x.z - mu) * rs * gg.z + bb.z;
    y.w = (x.w - mu) * rs * gg.w + bb.w;
    *((float4*)(o + row * 1024) + t) = y;
    if (oh) {
        __half2* ph = (__half2*)(oh + row * 1024);
        ph[2 * t]     = __floats2half2_rn(y.x, y.y);
        ph[2 * t + 1] = __floats2half2_rn(y.z, y.w);
    }
}

// ---------------- driver --------------------------------------------------------
extern "C" void kernel_launch(void* const* d_in, const int* in_sizes, int n_in,
                              void* d_out, int out_size)
{
    const float* x    = (const float*)d_in[0];
    const float* cb   = (const float*)d_in[1];
    const float* pb   = (const float*)d_in[2];
    const float* rpe  = (const float*)d_in[3];
    const float* Wq   = (const float*)d_in[4];
    const float* Wk   = (const float*)d_in[5];
    const float* Wv   = (const float*)d_in[6];
    const float* Wr   = (const float*)d_in[7];
    const float* Wo   = (const float*)d_in[8];
    const float* ln1g = (const float*)d_in[9];
    const float* ln1b = (const float*)d_in[10];
    const float* Wi   = (const float*)d_in[11];
    const float* bi   = (const float*)d_in[12];
    const float* Wout = (const float*)d_in[13];
    const float* bout = (const float*)d_in[14];
    const float* ln2g = (const float*)d_in[15];
    const float* ln2b = (const float*)d_in[16];
    float* out = (float*)d_out;

    __half *xh,*rpeh,*qkv,*qc,*qp,*r,*vt,*attn,*h1h,*inner;
    __half *WqkvT,*WrT,*WoT,*WiT,*WoutT;
    float *h1,*tmp,*opart,*ml;
    cudaGetSymbolAddress((void**)&xh, g_xh);      cudaGetSymbolAddress((void**)&rpeh, g_rpeh);
    cudaGetSymbolAddress((void**)&qkv, g_qkv);    cudaGetSymbolAddress((void**)&qc, g_qc);
    cudaGetSymbolAddress((void**)&qp, g_qp);      cudaGetSymbolAddress((void**)&r, g_r);
    cudaGetSymbolAddress((void**)&vt, g_vt);      cudaGetSymbolAddress((void**)&attn, g_attn);
    cudaGetSymbolAddress((void**)&opart, g_opart);cudaGetSymbolAddress((void**)&ml, g_ml);
    cudaGetSymbolAddress((void**)&h1, g_h1);      cudaGetSymbolAddress((void**)&h1h, g_h1h);
    cudaGetSymbolAddress((void**)&inner, g_inner);cudaGetSymbolAddress((void**)&tmp, g_tmp);
    cudaGetSymbolAddress((void**)&WqkvT, g_WqkvT);cudaGetSymbolAddress((void**)&WrT, g_WrT);
    cudaGetSymbolAddress((void**)&WoT, g_WoT);    cudaGetSymbolAddress((void**)&WiT, g_WiT);
    cudaGetSymbolAddress((void**)&WoutT, g_WoutT);

    cudaFuncSetAttribute((const void*)hgemm<128,2,4,0,1>,
                         cudaFuncAttributeMaxDynamicSharedMemorySize, HG_SMEM);
    cudaFuncSetAttribute((const void*)hgemm<128,2,4,0,0>,
                         cudaFuncAttributeMaxDynamicSharedMemorySize, HG_SMEM);
    cudaFuncSetAttribute((const void*)hgemm<128,2,4,2,1>,
                         cudaFuncAttributeMaxDynamicSharedMemorySize, HG_SMEM);
    cudaFuncSetAttribute(flash_k, cudaFuncAttributeMaxDynamicSharedMemorySize, FL_SMEM);

    static cudaStream_t s1 = nullptr, s2 = nullptr, s3 = nullptr;
    static cudaEvent_t  eF = nullptr, e1 = nullptr, e2 = nullptr, e3 = nullptr;
    if (s1 == nullptr) {
        cudaStreamCreateWithFlags(&s1, cudaStreamNonBlocking);
        cudaStreamCreateWithFlags(&s2, cudaStreamNonBlocking);
        cudaStreamCreateWithFlags(&s3, cudaStreamNonBlocking);
        cudaEventCreateWithFlags(&eF, cudaEventDisableTiming);
        cudaEventCreateWithFlags(&e1, cudaEventDisableTiming);
        cudaEventCreateWithFlags(&e2, cudaEventDisableTiming);
        cudaEventCreateWithFlags(&e3, cudaEventDisableTiming);
    }

    const int M = B_ * S_;
    dim3 blk(256);
    const long long Z0 = 0;

    cudaEventRecord(eF, 0);
    cudaStreamWaitEvent(s1, eF, 0);
    cudaStreamWaitEvent(s2, eF, 0);
    cudaStreamWaitEvent(s3, eF, 0);

    f2h_k<<<M * E_ / 1024, blk>>>(x, xh);

    transpose_h16<<<dim3(32, 32), dim3(32, 8), 0, s1>>>(Wq, WqkvT,               E_, NH_);
    transpose_h16<<<dim3(32, 32), dim3(32, 8), 0, s1>>>(Wk, WqkvT + 1024 * 1024, E_, NH_);
    transpose_h16<<<dim3(32, 32), dim3(32, 8), 0, s1>>>(Wv, WqkvT + 2048 * 1024, E_, NH_);
    cudaEventRecord(e1, s1);

    f2h_k<<<B_ * R_ * E_ / 1024, blk, 0, s2>>>(rpe, rpeh);
    transpose_h16<<<dim3(32, 32), dim3(32, 8), 0, s2>>>(Wr, WrT, E_, NH_);
    hgemm<128,2,4,0,1><<<dim3(8,64,1), blk, HG_SMEM, s2>>>(
        rpeh, WrT, r, nullptr, nullptr, nullptr, nullptr, E_, E_, E_, NH_,
        1, Z0,Z0,Z0,Z0,Z0,Z0, 0, 1.f);
    cudaEventRecord(e2, s2);

    transpose_h16<<<dim3(32, 32),  dim3(32, 8), 0, s3>>>(Wo,   WoT,   NH_, E_);
    transpose_h16<<<dim3(128, 32), dim3(32, 8), 0, s3>>>(Wi,   WiT,   E_, F_);
    transpose_h16<<<dim3(32, 128), dim3(32, 8), 0, s3>>>(Wout, WoutT, F_, E_);
    cudaEventRecord(e3, s3);

    cudaStreamWaitEvent(0, e1, 0);
    hgemm<128,2,4,2,1><<<dim3(24,32,1), blk, HG_SMEM>>>(
        xh, WqkvT, qkv, cb, pb, qc, qp, E_, E_, E_, 3*NH_,
        1, Z0,Z0,Z0,Z0,Z0,Z0, 0, 1.f);
    transpose_vh<<<dim3(S_/32, 2, B_*NHEADS), dim3(32,8)>>>(qkv + 2*NH_, vt, S_, 3*NH_);

    // split-KV flash: 1024 half-CTAs, then merge
    cudaStreamWaitEvent(0, e2, 0);
    flash_k<<<dim3(8, B_ * NHEADS, 2), blk, FL_SMEM>>>(qc, qp, qkv + NH_, vt, r,
                                                       opart, ml, 3*NH_);
    combine_k<<<B_ * NHEADS * S_ / 8, blk>>>(opart, ml, attn);

    cudaStreamWaitEvent(0, e3, 0);
    hgemm<128,2,4,0,0><<<dim3(8,32,1), blk, HG_SMEM>>>(
        attn, WoT, tmp, nullptr, nullptr, nullptr, nullptr, NH_, NH_, NH_, E_,
        1, Z0,Z0,Z0,Z0,Z0,Z0, 0, 1.f);
    ln_k<<<M, 256>>>(tmp, x, ln1g, ln1b, h1, h1h);

    hgemm<128,2,4,0,1><<<dim3(32,32,1), blk, HG_SMEM>>>(
        h1h, WiT, inner, bi, nullptr, nullptr, nullptr, E_, E_, E_, F_,
        1, Z0,Z0,Z0,Z0,Z0,Z0, 1, 1.f);
    hgemm<128,2,4,0,0><<<dim3(8,32,1), blk, HG_SMEM>>>(
        inner, WoutT, tmp, bout, nullptr, nullptr, nullptr, F_, F_, F_, E_,
        1, Z0,Z0,Z0,Z0,Z0,Z0, 0, 1.f);
    ln_k<<<M, 256>>>(tmp, h1, ln2g, ln2b, out, nullptr);
}

// round 16
// speedup vs baseline: 1.0634x; 1.0004x over previous
#include <cuda_runtime.h>
#include <cuda_fp16.h>
#include <math.h>
#include <stdint.h>

#define B_      4
#define S_      1024
#define E_      1024
#define NHEADS  16
#define H_      64
#define NH_     1024
#define F_      4096
#define R_      2048

// ---------------- scratch (static device globals) ----------------
__device__ __half g_xh[4194304];
__device__ __half g_rpeh[8388608];
__device__ __half g_qkv[12582912];     // [B,S,3NH]
__device__ __half g_qc[4194304];
__device__ __half g_qp[4194304];
__device__ __half g_r[8388608];
__device__ __half g_vt[4194304];       // [B,N,H,S]
__device__ __half g_attn[4194304];
__device__ float  g_opart[8388608];    // [2][z*S + i][H]
__device__ float  g_ml[262144];        // [2][row][m,l]
__device__ float  g_h1[4194304];
__device__ __half g_h1h[4194304];
__device__ __half g_inner[16777216];
__device__ float  g_tmp[4194304];
__device__ float  g_tmp2[4194304];
__device__ __half g_WqkvT[3145728];
__device__ __half g_WrT[1048576];
__device__ __half g_WoT[1048576];
__device__ __half g_WiT[4194304];
__device__ __half g_WoutT[4194304];

// ---------------- helpers ----------------
__device__ __forceinline__ uint32_t smem_u32(const void* p) {
    uint32_t a;
    asm("{ .reg .u64 t; cvta.to.shared.u64 t, %1; cvt.u32.u64 %0, t; }" : "=r"(a) : "l"(p));
    return a;
}
__device__ __forceinline__ void cpasync16(uint32_t s, const void* g) {
    asm volatile("cp.async.cg.shared.global [%0], [%1], 16;" :: "r"(s), "l"(g));
}
#define CP_COMMIT() asm volatile("cp.async.commit_group;" ::: "memory")
#define CP_WAIT(n)  asm volatile("cp.async.wait_group %0;" :: "n"(n) : "memory")

#define LDM4(r0, r1, r2, r3, a)                                                     \
    asm volatile("ldmatrix.sync.aligned.m8n8.x4.shared.b16 {%0,%1,%2,%3}, [%4];"    \
                 : "=r"(r0), "=r"(r1), "=r"(r2), "=r"(r3) : "r"(a))

#define MMA16816(c, a, b)                                                           \
    asm volatile("mma.sync.aligned.m16n8k16.row.col.f32.f16.f16.f32 "               \
                 "{%0,%1,%2,%3},{%4,%5,%6,%7},{%8,%9},{%0,%1,%2,%3};"               \
                 : "+f"((c)[0]), "+f"((c)[1]), "+f"((c)[2]), "+f"((c)[3])           \
                 : "r"((a)[0]), "r"((a)[1]), "r"((a)[2]), "r"((a)[3]),              \
                   "r"((b)[0]), "r"((b)[1]))

// exp on FMA/ALU pipes; common-mode error cancels in softmax normalization.
__device__ __forceinline__ float fast_exp(float x) {
    float t = fmaxf(x * 1.44269504f, -126.f);
    float fl = floorf(t);
    float f = t - fl;
    float p = fmaf(f, 0.0792345f, 0.2248712f);
    p = fmaf(f, p, 0.6958943f);
    p = fmaf(f, p, 1.0f);
    return __int_as_float(__float_as_int(p) + (((int)fl) << 23));
}

// ---------------- fp16 tensor-core GEMM, K-chunk 64, 3-stage ring ---------------
#define LDSG 72
#define HG_SMEM (3 * (128 + 128) * LDSG * 2)
template<int BN, int WRM, int WRN, int EPI, int OUTH>
__global__ __launch_bounds__(256, 2) void hgemm(
    const __half* __restrict__ A, const __half* __restrict__ Bm,
    void* __restrict__ Cv, const float* __restrict__ bias,
    const float* __restrict__ pb, __half* __restrict__ qcp, __half* __restrict__ qpp,
    int K, int lda, int ldb, int ldc, int zdiv,
    long long As1, long long As2, long long Bs1, long long Bs2,
    long long Cs1, long long Cs2, int relu, float scale)
{
    constexpr int BM = 128;
    constexpr int MW = BM / WRM, NW = BN / WRN;
    constexpr int MT = MW / 16, NPAIR = NW / 16, NT = NW / 8;
    extern __shared__ __half hsm[];
    __half* sA = hsm;
    __half* sB = hsm + 3 * BM * LDSG;

    const int bm = blockIdx.y * BM, bn = blockIdx.x * BN;
    {
        int z = blockIdx.z, zq = z / zdiv, zr = z % zdiv;
        A  += zq * As1 + zr * As2;
        Bm += zq * Bs1 + zr * Bs2;
    }
    const int tid = threadIdx.x, lane = tid & 31, wid = tid >> 5;
    const int wm = (wid / WRN) * MW, wn = (wid % WRN) * NW;

    float cf[MT][NT][4];
#pragma unroll
    for (int i = 0; i < MT; i++)
#pragma unroll
        for (int j = 0; j < NT; j++)
#pragma unroll
            for (int e = 0; e < 4; e++) cf[i][j][e] = 0.f;

    auto stage = [&](int c, int sx) {
        __half* dA = sA + sx * BM * LDSG;
        __half* dB = sB + sx * BN * LDSG;
#pragma unroll
        for (int i = 0; i < BM * 8 / 256; i++) {
            int id = tid + i * 256, row = id >> 3, ch = id & 7;
            cpasync16(smem_u32(dA + row * LDSG + ch * 8),
                      A + (long long)(bm + row) * lda + c * 64 + ch * 8);
        }
#pragma unroll
        for (int i = 0; i < BN * 8 / 256; i++) {
            int id = tid + i * 256, row = id >> 3, ch = id & 7;
            cpasync16(smem_u32(dB + row * LDSG + ch * 8),
                      Bm + (long long)(bn + row) * ldb + c * 64 + ch * 8);
        }
        CP_COMMIT();
    };

    const int nkt = K >> 6;
    stage(0, 0);
    stage(1, 1);
    int cbuf = 0, pbuf = 2;
    for (int c = 0; c < nkt; c++) {
        CP_WAIT(1);
        __syncthreads();
        if (c + 2 < nkt) stage(c + 2, pbuf);
        else CP_COMMIT();
        const uint32_t a0 = smem_u32(sA + cbuf * BM * LDSG);
        const uint32_t b0 = smem_u32(sB + cbuf * BN * LDSG);
#pragma unroll
        for (int ks = 0; ks < 4; ks++) {
            uint32_t af[MT][4], bf[NT][2];
#pragma unroll
            for (int mt = 0; mt < MT; mt++) {
                uint32_t ad = a0 + ((wm + mt * 16 + (lane & 15)) * LDSG
                                    + ks * 16 + (lane >> 4) * 8) * 2;
                LDM4(af[mt][0], af[mt][1], af[mt][2], af[mt][3], ad);
            }
#pragma unroll
            for (int p = 0; p < NPAIR; p++) {
                int rn = wn + p * 16 + (lane & 7) + ((lane >> 4) << 3);
                uint32_t bd = b0 + (rn * LDSG + ks * 16 + ((lane >> 3) & 1) * 8) * 2;
                uint32_t r0, r1, r2, r3;
                LDM4(r0, r1, r2, r3, bd);
                bf[2 * p][0] = r0; bf[2 * p][1] = r1;
                bf[2 * p + 1][0] = r2; bf[2 * p + 1][1] = r3;
            }
#pragma unroll
            for (int mt = 0; mt < MT; mt++)
#pragma unroll
                for (int nt = 0; nt < NT; nt++)
                    MMA16816(cf[mt][nt], af[mt], bf[nt]);
        }
        cbuf = cbuf == 2 ? 0 : cbuf + 1;
        pbuf = pbuf == 2 ? 0 : pbuf + 1;
    }

    long long coff;
    {
        int z = blockIdx.z, zq = z / zdiv, zr = z % zdiv;
        coff = zq * Cs1 + zr * Cs2;
    }
#pragma unroll
    for (int mt = 0; mt < MT; mt++) {
#pragma unroll
        for (int nt = 0; nt < NT; nt++) {
            int r = bm + wm + mt * 16 + (lane >> 2);
            int col = bn + wn + nt * 8 + (lane & 3) * 2;
#pragma unroll
            for (int e2 = 0; e2 < 2; e2++) {
                int row = r + 8 * e2;
                float v0 = cf[mt][nt][e2 * 2] * scale;
                float v1 = cf[mt][nt][e2 * 2 + 1] * scale;
                if (EPI == 2) {
                    if (col < NH_) {
                        float c0 = bias[col], c1 = bias[col + 1];
                        float p0 = pb[col],  p1 = pb[col + 1];
                        *(__half2*)(qcp + (long long)row * NH_ + col) =
                            __floats2half2_rn((v0 + c0) * 0.125f, (v1 + c1) * 0.125f);
                        *(__half2*)(qpp + (long long)row * NH_ + col) =
                            __floats2half2_rn((v0 + p0) * 0.125f, (v1 + p1) * 0.125f);
                    } else {
                        __half* Ch = (__half*)Cv;
                        *(__half2*)(Ch + (long long)row * ldc + col) =
                            __floats2half2_rn(v0, v1);
                    }
                } else {
                    if (bias) { v0 += bias[col]; v1 += bias[col + 1]; }
                    if (relu) { v0 = fmaxf(v0, 0.f); v1 = fmaxf(v1, 0.f); }
                    if (OUTH) {
                        __half* Ch = (__half*)Cv + coff;
                        *(__half2*)(Ch + (long long)row * ldc + col) =
                            __floats2half2_rn(v0, v1);
                    } else {
                        float* Cf = (float*)Cv + coff;
                        *(float2*)(Cf + (long long)row * ldc + col) = make_float2(v0, v1);
                    }
                }
            }
        }
    }
}

// ---------------- flash attention, split-KV halves ------------------------------
#define LDQ_  72
#define LDV_  136
#define LDS_S 132
#define LDP_  136
#define FL_SMEM (3*128*LDQ_*2 + 64*LDV_*2 + 256*LDQ_*2 + 128*LDS_S*4 + 128*LDP_*2 + 3*128*4)

__global__ __launch_bounds__(256, 1) void flash_k(
    const __half* __restrict__ qc, const __half* __restrict__ qp,
    const __half* __restrict__ kk, const __half* __restrict__ vt,
    const __half* __restrict__ rr, float* __restrict__ opart,
    float* __restrict__ ml, int kstr)
{
    extern __shared__ char smraw[];
    __half* sQc = (__half*)smraw;
    __half* sQp = sQc + 128 * LDQ_;
    __half* sK  = sQp + 128 * LDQ_;
    __half* sV  = sK  + 128 * LDQ_;
    __half* sR  = sV  + 64 * LDV_;
    float*  sS  = (float*)(sR + 256 * LDQ_);
    __half* sP  = (__half*)(sS + 128 * LDS_S);
    float*  sM  = (float*)(sP + 128 * LDP_);
    float*  sL  = sM + 128;
    float*  sAl = sL + 128;

    const int it = blockIdx.x, z = blockIdx.y, hfk = blockIdx.z;
    const int b = z >> 4, n = z & 15;
    const int i0 = it * 128;
    const int jbeg = hfk * 4, jend = jbeg + 4;
    const int tid = threadIdx.x, lane = tid & 31, wid = tid >> 5;
    const int wm = wid * 16;

    int ntlo0 = (105 - wm + 7) >> 3; if (ntlo0 < 0) ntlo0 = 0;
    int nthi1 = (126 - wm) >> 3;

    const __half* qcb = qc + (long long)b * S_ * NH_ + n * H_;
    const __half* qpb = qp + (long long)b * S_ * NH_ + n * H_;
    const __half* kb  = kk + (long long)b * S_ * kstr + n * H_;
    const __half* vtb = vt + (long long)z * H_ * S_;
    const __half* rb  = rr + (long long)b * R_ * NH_ + n * H_;

    auto stageK = [&](int jt) {
        const int j0 = jt * 128;
        if (jt < jend) {
#pragma unroll
            for (int i = 0; i < 4; i++) {
                int id = tid + i * 256, row = id >> 3, ch = id & 7;
                cpasync16(smem_u32(sK + row * LDQ_ + ch * 8),
                          kb + (long long)(j0 + row) * kstr + ch * 8);
            }
        }
        CP_COMMIT();
    };
    auto stageR = [&](int jt) {
        const int base = S_ + jt * 128 - i0 - 127;
        if (jt < jend) {
#pragma unroll
            for (int i = 0; i < 8; i++) {
                int id = tid + i * 256, row = id >> 3, ch = id & 7;
                int grow = base + row; grow = grow < R_ ? grow : R_ - 1;
                cpasync16(smem_u32(sR + row * LDQ_ + ch * 8),
                          rb + (long long)grow * NH_ + ch * 8);
            }
        }
        CP_COMMIT();
    };
    auto stageV = [&](int jt) {
        const int j0 = jt * 128;
        if (jt < jend) {
#pragma unroll
            for (int i = 0; i < 4; i++) {
                int id = tid + i * 256, row = id >> 4, ch = id & 15;
                cpasync16(smem_u32(sV + row * LDV_ + ch * 8),
                          vtb + (long long)row * S_ + j0 + ch * 8);
            }
        }
        CP_COMMIT();
    };

#pragma unroll
    for (int i = 0; i < 4; i++) {
        int id = tid + i * 256, row = id >> 3, ch = id & 7;
        cpasync16(smem_u32(sQc + row * LDQ_ + ch * 8),
                  qcb + (long long)(i0 + row) * NH_ + ch * 8);
        cpasync16(smem_u32(sQp + row * LDQ_ + ch * 8),
                  qpb + (long long)(i0 + row) * NH_ + ch * 8);
    }
    stageK(jbeg);
    stageR(jbeg);
    stageV(jbeg);
    if (tid < 128) { sM[tid] = -1e30f; sL[tid] = 0.f; }

    float of[8][4];
#pragma unroll
    for (int nt = 0; nt < 8; nt++)
#pragma unroll
        for (int e = 0; e < 4; e++) of[nt][e] = 0.f;

    const uint32_t aQc = smem_u32(sQc), aQp = smem_u32(sQp);
    const uint32_t aK = smem_u32(sK), aV = smem_u32(sV);
    const uint32_t aR = smem_u32(sR), aP = smem_u32(sP);

    for (int jt = jbeg; jt < jend; jt++) {
        CP_WAIT(2);
        __syncthreads();

        float cf[16][4];
#pragma unroll
        for (int nt = 0; nt < 16; nt++)
#pragma unroll
            for (int e = 0; e < 4; e++) cf[nt][e] = 0.f;
#pragma unroll
        for (int ks = 0; ks < 4; ks++) {
            uint32_t af[4], bf[16][2];
            LDM4(af[0], af[1], af[2], af[3],
                 aQc + ((wm + (lane & 15)) * LDQ_ + ks * 16 + (lane >> 4) * 8) * 2);
#pragma unroll
            for (int p = 0; p < 8; p++) {
                int rn = p * 16 + (lane & 7) + ((lane >> 4) << 3);
                uint32_t r0, r1, r2, r3;
                LDM4(r0, r1, r2, r3, aK + (rn * LDQ_ + ks * 16 + ((lane >> 3) & 1) * 8) * 2);
                bf[2 * p][0] = r0; bf[2 * p][1] = r1;
                bf[2 * p + 1][0] = r2; bf[2 * p + 1][1] = r3;
            }
#pragma unroll
            for (int nt = 0; nt < 16; nt++) MMA16816(cf[nt], af, bf[nt]);
        }
#pragma unroll
        for (int nt = 0; nt < 16; nt++) {
            int c0 = nt * 8 + (lane & 3) * 2;
#pragma unroll
            for (int e2 = 0; e2 < 2; e2++) {
                int row = wm + (lane >> 2) + 8 * e2;
                *(float2*)&sS[row * LDS_S + c0] = make_float2(cf[nt][e2 * 2], cf[nt][e2 * 2 + 1]);
            }
        }

        CP_WAIT(1);
        __syncthreads();
        stageK(jt + 1);

#pragma unroll
        for (int halfg = 0; halfg < 2; halfg++) {
            int g0 = halfg * 128;
            int lo = halfg == 0 ? ntlo0 : 0;
            int hi = halfg == 0 ? 15 : nthi1;
#pragma unroll
            for (int nt = 0; nt < 16; nt++)
#pragma unroll
                for (int e = 0; e < 4; e++) cf[nt][e] = 0.f;
#pragma unroll
            for (int ks = 0; ks < 4; ks++) {
                uint32_t af[4], bf[16][2];
                LDM4(af[0], af[1], af[2], af[3],
                     aQp + ((wm + (lane & 15)) * LDQ_ + ks * 16 + (lane >> 4) * 8) * 2);
#pragma unroll
                for (int p = 0; p < 8; p++) {
                    if (2 * p + 1 < lo || 2 * p > hi) continue;
                    int rn = g0 + p * 16 + (lane & 7) + ((lane >> 4) << 3);
                    uint32_t r0, r1, r2, r3;
                    LDM4(r0, r1, r2, r3, aR + (rn * LDQ_ + ks * 16 + ((lane >> 3) & 1) * 8) * 2);
                    bf[2 * p][0] = r0; bf[2 * p][1] = r1;
                    bf[2 * p + 1][0] = r2; bf[2 * p + 1][1] = r3;
                }
#pragma unroll
                for (int nt = 0; nt < 16; nt++) {
                    if (nt < lo || nt > hi) continue;
                    MMA16816(cf[nt], af, bf[nt]);
                }
            }
#pragma unroll
            for (int nt = 0; nt < 16; nt++) {
                if (nt < lo || nt > hi) continue;
#pragma unroll
                for (int e = 0; e < 4; e++) {
                    int li = wm + (lane >> 2) + 8 * (e >> 1);
                    int g  = g0 + nt * 8 + (lane & 3) * 2 + (e & 1);
                    int lj = g - 127 + li;
                    if (lj >= 0 && lj < 128) sS[li * LDS_S + lj] += cf[nt][e];
                }
            }
            __syncwarp();
        }

        CP_WAIT(1);
        __syncthreads();
        stageR(jt + 1);

        {
            int rloc = wm + (lane >> 1), hf = lane & 1;
            float* srow = &sS[rloc * LDS_S + hf * 64];
            float4* srow4 = (float4*)srow;
            float m0 = -1e30f, m1 = -1e30f, m2 = -1e30f, m3 = -1e30f;
#pragma unroll
            for (int c = 0; c < 16; c += 2) {
                float4 a = srow4[c], bq = srow4[c + 1];
                m0 = fmaxf(m0, fmaxf(a.x, a.y));
                m1 = fmaxf(m1, fmaxf(a.z, a.w));
                m2 = fmaxf(m2, fmaxf(bq.x, bq.y));
                m3 = fmaxf(m3, fmaxf(bq.z, bq.w));
            }
            float mx = fmaxf(fmaxf(m0, m1), fmaxf(m2, m3));
            mx = fmaxf(mx, __shfl_xor_sync(0xffffffffu, mx, 1));
            float mold = sM[rloc];
            float mnew = fmaxf(mold, mx);
            float alpha = fast_exp(mold - mnew);
            float s0 = 0.f, s1 = 0.f;
            __half* prow = &sP[rloc * LDP_ + hf * 64];
#pragma unroll
            for (int c = 0; c < 16; c++) {
                float4 a = srow4[c];
                float p0 = fast_exp(a.x - mnew);
                float p1 = fast_exp(a.y - mnew);
                float p2 = fast_exp(a.z - mnew);
                float p3 = fast_exp(a.w - mnew);
                s0 += p0 + p1;
                s1 += p2 + p3;
                *(__half2*)&prow[c * 4]     = __floats2half2_rn(p0, p1);
                *(__half2*)&prow[c * 4 + 2] = __floats2half2_rn(p2, p3);
            }
            float sum = s0 + s1;
            sum += __shfl_xor_sync(0xffffffffu, sum, 1);
            if (hf == 0) {
                sL[rloc] = sL[rloc] * alpha + sum;
                sM[rloc] = mnew;
                sAl[rloc] = alpha;
            }
        }
        __syncwarp();

#pragma unroll
        for (int e2 = 0; e2 < 2; e2++) {
            float al = sAl[wm + (lane >> 2) + 8 * e2];
#pragma unroll
            for (int nt = 0; nt < 8; nt++) {
                of[nt][e2 * 2]     *= al;
                of[nt][e2 * 2 + 1] *= al;
            }
        }
#pragma unroll
        for (int ks = 0; ks < 8; ks++) {
            uint32_t af[4], bfv[8][2];
            LDM4(af[0], af[1], af[2], af[3],
                 aP + ((wm + (lane & 15)) * LDP_ + ks * 16 + (lane >> 4) * 8) * 2);
#pragma unroll
            for (int p = 0; p < 4; p++) {
                int rn = p * 16 + (lane & 7) + ((lane >> 4) << 3);
                uint32_t r0, r1, r2, r3;
                LDM4(r0, r1, r2, r3, aV + (rn * LDV_ + ks * 16 + ((lane >> 3) & 1) * 8) * 2);
                bfv[2 * p][0] = r0; bfv[2 * p][1] = r1;
                bfv[2 * p + 1][0] = r2; bfv[2 * p + 1][1] = r3;
            }
#pragma unroll
            for (int nt = 0; nt < 8; nt++) MMA16816(of[nt], af, bfv[nt]);
        }
        __syncthreads();
        stageV(jt + 1);
    }

    long long hoff = (long long)hfk * 4194304;
#pragma unroll
    for (int e2 = 0; e2 < 2; e2++) {
        int li = wm + (lane >> 2) + 8 * e2;
        long long rowg = (long long)z * S_ + i0 + li;
#pragma unroll
        for (int nt = 0; nt < 8; nt++) {
            int col = nt * 8 + (lane & 3) * 2;
            *(float2*)(opart + hoff + rowg * H_ + col) =
                make_float2(of[nt][e2 * 2], of[nt][e2 * 2 + 1]);
        }
        if ((lane & 3) == 0) {
            ml[(long long)hfk * 131072 + rowg * 2]     = sM[li];
            ml[(long long)hfk * 131072 + rowg * 2 + 1] = sL[li];
        }
    }
}

// ---------------- split-KV combine ----------------------------------------------
__global__ __launch_bounds__(256) void combine_k(
    const float* __restrict__ opart, const float* __restrict__ ml,
    __half* __restrict__ attn)
{
    int row = blockIdx.x * 8 + (threadIdx.x >> 5);
    int lane = threadIdx.x & 31;
    int z = row >> 10, i = row & 1023;
    int b = z >> 4, n = z & 15;
    float m1 = ml[row * 2],          l1 = ml[row * 2 + 1];
    float m2 = ml[131072 + row * 2], l2 = ml[131072 + row * 2 + 1];
    float m = fmaxf(m1, m2);
    float a1 = fast_exp(m1 - m), a2 = fast_exp(m2 - m);
    float inv = 1.0f / fmaf(a1, l1, a2 * l2);
    float2 v1 = *(const float2*)(opart + (long long)row * H_ + lane * 2);
    float2 v2 = *(const float2*)(opart + 4194304 + (long long)row * H_ + lane * 2);
    float o0 = fmaf(a1, v1.x, a2 * v2.x) * inv;
    float o1 = fmaf(a1, v1.y, a2 * v2.y) * inv;
    *(__half2*)(attn + (long long)(b * S_ + i) * NH_ + n * H_ + lane * 2) =
        __floats2half2_rn(o0, o1);
}

// ---------------- fp32 -> fp16 copy ----------------
__global__ __launch_bounds__(256) void f2h_k(const float* __restrict__ in,
                                             __half* __restrict__ out)
{
    long long i = (long long)blockIdx.x * 256 + threadIdx.x;
    float4 v = ((const float4*)in)[i];
    ((__half2*)out)[i * 2]     = __floats2half2_rn(v.x, v.y);
    ((__half2*)out)[i * 2 + 1] = __floats2half2_rn(v.z, v.w);
}

// ---------------- fp32 transpose -> fp16 ----------------
__global__ void transpose_h16(const float* __restrict__ in, __half* __restrict__ out,
                              int rows, int cols)
{
    __shared__ float tile[32][33];
    int r0 = blockIdx.y * 32, c0 = blockIdx.x * 32;
    int tx = threadIdx.x, ty = threadIdx.y;
#pragma unroll
    for (int i = 0; i < 4; i++)
        tile[ty + i * 8][tx] = in[(long long)(r0 + ty + i * 8) * cols + c0 + tx];
    __syncthreads();
#pragma unroll
    for (int i = 0; i < 4; i++)
        out[(long long)(c0 + ty + i * 8) * rows + r0 + tx] = __float2half_rn(tile[tx][ty + i * 8]);
}

// ---------------- per-head half transpose ----------------
__global__ void transpose_vh(const __half* __restrict__ in, __half* __restrict__ out,
                             int rows, int instr)
{
    __shared__ __half tile[32][34];
    int z = blockIdx.z, b = z >> 4, n = z & 15;
    const __half* ip = in + (long long)b * rows * instr + n * H_;
    __half* op = out + (long long)z * H_ * rows;
    int r0 = blockIdx.x * 32, h0 = blockIdx.y * 32;
    int tx = threadIdx.x, ty = threadIdx.y;
#pragma unroll
    for (int i = 0; i < 4; i++)
        tile[ty + i * 8][tx] = ip[(long long)(r0 + ty + i * 8) * instr + h0 + tx];
    __syncthreads();
#pragma unroll
    for (int i = 0; i < 4; i++)
        op[(long long)(h0 + ty + i * 8) * rows + r0 + tx] = tile[tx][ty + i * 8];
}

// ---------------- residual + LayerNorm (a [+a2] + res; optional fp16 copy) ------
__global__ __launch_bounds__(256) void ln_k(
    const float* __restrict__ a, const float* __restrict__ a2,
    const float* __restrict__ res,
    const float* __restrict__ g, const float* __restrict__ bt,
    float* __restrict__ o, __half* __restrict__ oh)
{
    __shared__ float red[16];
    long long row = blockIdx.x;
    int t = threadIdx.x;
    float4 va = *((const float4*)(a + row * 1024) + t);
    float4 vr = *((const float4*)(res + row * 1024) + t);
    float4 x;
    x.x = va.x + vr.x; x.y = va.y + vr.y; x.z = va.z + vr.z; x.w = va.w + vr.w;
    if (a2) {
        float4 v2 = *((const float4*)(a2 + row * 1024) + t);
        x.x += v2.x; x.y += v2.y; x.z += v2.z; x.w += v2.w;
    }
    float s  = x.x + x.y + x.z + x.w;
    float q2 = x.x * x.x + x.y * x.y + x.z * x.z + x.w * x.w;
#pragma unroll
    for (int off = 16; off; off >>= 1) {
        s  += __shfl_xor_sync(0xffffffffu, s, off);
        q2 += __shfl_xor_sync(0xffffffffu, q2, off);
    }
    if ((t & 31) == 0) { red[t >> 5] = s; red[8 + (t >> 5)] = q2; }
    __syncthreads();
    if (t == 0) {
        float ss = red[0], qq = red[8];
#pragma unroll
        for (int i = 1; i < 8; i++) { ss += red[i]; qq += red[8 + i]; }
        red[0] = ss; red[8] = qq;
    }
    __syncthreads();
    float mu  = red[0] * (1.f / 1024.f);
    float var = red[8] * (1.f / 1024.f) - mu * mu;
    float rs = rsqrtf(var + 1e-12f);
    float4 gg = *((const float4*)g + t);
    float4 bb = *((const float4*)bt + t);
    float4 y;
    y.x = (x.x - mu) * rs * gg.x + bb.x;
    y.y = (x.y - mu) * rs * gg.y + bb.y;
    y.z = (x.z - mu) * rs * gg.z + bb.z;
    y.w = (x.w - mu) * rs * gg.w + bb.w;
    *((float4*)(o + row * 1024) + t) = y;
    if (oh) {
        __half2* ph = (__half2*)(oh + row * 1024);
        ph[2 * t]     = __floats2half2_rn(y.x, y.y);
        ph[2 * t + 1] = __floats2half2_rn(y.z, y.w);
    }
}

// ---------------- driver --------------------------------------------------------
extern "C" void kernel_launch(void* const* d_in, const int* in_sizes, int n_in,
                              void* d_out, int out_size)
{
    const float* x    = (const float*)d_in[0];
    const float* cb   = (const float*)d_in[1];
    const float* pb   = (const float*)d_in[2];
    const float* rpe  = (const float*)d_in[3];
    const float* Wq   = (const float*)d_in[4];
    const float* Wk   = (const float*)d_in[5];
    const float* Wv   = (const float*)d_in[6];
    const float* Wr   = (const float*)d_in[7];
    const float* Wo   = (const float*)d_in[8];
    const float* ln1g = (const float*)d_in[9];
    const float* ln1b = (const float*)d_in[10];
    const float* Wi   = (const float*)d_in[11];
    const float* bi   = (const float*)d_in[12];
    const float* Wout = (const float*)d_in[13];
    const float* bout = (const float*)d_in[14];
    const float* ln2g = (const float*)d_in[15];
    const float* ln2b = (const float*)d_in[16];
    float* out = (float*)d_out;

    __half *xh,*rpeh,*qkv,*qc,*qp,*r,*vt,*attn,*h1h,*inner;
    __half *WqkvT,*WrT,*WoT,*WiT,*WoutT;
    float *h1,*tmp,*tmp2,*opart,*ml;
    cudaGetSymbolAddress((void**)&xh, g_xh);      cudaGetSymbolAddress((void**)&rpeh, g_rpeh);
    cudaGetSymbolAddress((void**)&qkv, g_qkv);    cudaGetSymbolAddress((void**)&qc, g_qc);
    cudaGetSymbolAddress((void**)&qp, g_qp);      cudaGetSymbolAddress((void**)&r, g_r);
    cudaGetSymbolAddress((void**)&vt, g_vt);      cudaGetSymbolAddress((void**)&attn, g_attn);
    cudaGetSymbolAddress((void**)&opart, g_opart);cudaGetSymbolAddress((void**)&ml, g_ml);
    cudaGetSymbolAddress((void**)&h1, g_h1);      cudaGetSymbolAddress((void**)&h1h, g_h1h);
    cudaGetSymbolAddress((void**)&inner, g_inner);cudaGetSymbolAddress((void**)&tmp, g_tmp);
    cudaGetSymbolAddress((void**)&tmp2, g_tmp2);
    cudaGetSymbolAddress((void**)&WqkvT, g_WqkvT);cudaGetSymbolAddress((void**)&WrT, g_WrT);
    cudaGetSymbolAddress((void**)&WoT, g_WoT);    cudaGetSymbolAddress((void**)&WiT, g_WiT);
    cudaGetSymbolAddress((void**)&WoutT, g_WoutT);

    cudaFuncSetAttribute((const void*)hgemm<128,2,4,0,1>,
                         cudaFuncAttributeMaxDynamicSharedMemorySize, HG_SMEM);
    cudaFuncSetAttribute((const void*)hgemm<128,2,4,0,0>,
                         cudaFuncAttributeMaxDynamicSharedMemorySize, HG_SMEM);
    cudaFuncSetAttribute((const void*)hgemm<128,2,4,2,1>,
                         cudaFuncAttributeMaxDynamicSharedMemorySize, HG_SMEM);
    cudaFuncSetAttribute(flash_k, cudaFuncAttributeMaxDynamicSharedMemorySize, FL_SMEM);

    static cudaStream_t s1 = nullptr, s2 = nullptr, s3 = nullptr;
    static cudaEvent_t  eF = nullptr, e1 = nullptr, e2 = nullptr, e3 = nullptr;
    static cudaEvent_t  eLN = nullptr, eFB = nullptr;
    if (s1 == nullptr) {
        cudaStreamCreateWithFlags(&s1, cudaStreamNonBlocking);
        cudaStreamCreateWithFlags(&s2, cudaStreamNonBlocking);
        cudaStreamCreateWithFlags(&s3, cudaStreamNonBlocking);
        cudaEventCreateWithFlags(&eF, cudaEventDisableTiming);
        cudaEventCreateWithFlags(&e1, cudaEventDisableTiming);
        cudaEventCreateWithFlags(&e2, cudaEventDisableTiming);
        cudaEventCreateWithFlags(&e3, cudaEventDisableTiming);
        cudaEventCreateWithFlags(&eLN, cudaEventDisableTiming);
        cudaEventCreateWithFlags(&eFB, cudaEventDisableTiming);
    }

    const int M = B_ * S_;
    dim3 blk(256);
    const long long Z0 = 0;

    cudaEventRecord(eF, 0);
    cudaStreamWaitEvent(s1, eF, 0);
    cudaStreamWaitEvent(s2, eF, 0);
    cudaStreamWaitEvent(s3, eF, 0);

    f2h_k<<<M * E_ / 1024, blk>>>(x, xh);

    transpose_h16<<<dim3(32, 32), dim3(32, 8), 0, s1>>>(Wq, WqkvT,               E_, NH_);
    transpose_h16<<<dim3(32, 32), dim3(32, 8), 0, s1>>>(Wk, WqkvT + 1024 * 1024, E_, NH_);
    transpose_h16<<<dim3(32, 32), dim3(32, 8), 0, s1>>>(Wv, WqkvT + 2048 * 1024, E_, NH_);
    cudaEventRecord(e1, s1);

    f2h_k<<<B_ * R_ * E_ / 1024, blk, 0, s2>>>(rpe, rpeh);
    transpose_h16<<<dim3(32, 32), dim3(32, 8), 0, s2>>>(Wr, WrT, E_, NH_);
    hgemm<128,2,4,0,1><<<dim3(8,64,1), blk, HG_SMEM, s2>>>(
        rpeh, WrT, r, nullptr, nullptr, nullptr, nullptr, E_, E_, E_, NH_,
        1, Z0,Z0,Z0,Z0,Z0,Z0, 0, 1.f);
    cudaEventRecord(e2, s2);

    transpose_h16<<<dim3(32, 32),  dim3(32, 8), 0, s3>>>(Wo,   WoT,   NH_, E_);
    transpose_h16<<<dim3(128, 32), dim3(32, 8), 0, s3>>>(Wi,   WiT,   E_, F_);
    transpose_h16<<<dim3(32, 128), dim3(32, 8), 0, s3>>>(Wout, WoutT, F_, E_);
    cudaEventRecord(e3, s3);

    cudaStreamWaitEvent(0, e1, 0);
    hgemm<128,2,4,2,1><<<dim3(24,32,1), blk, HG_SMEM>>>(
        xh, WqkvT, qkv, cb, pb, qc, qp, E_, E_, E_, 3*NH_,
        1, Z0,Z0,Z0,Z0,Z0,Z0, 0, 1.f);
    transpose_vh<<<dim3(S_/32, 2, B_*NHEADS), dim3(32,8)>>>(qkv + 2*NH_, vt, S_, 3*NH_);

    cudaStreamWaitEvent(0, e2, 0);
    flash_k<<<dim3(8, B_ * NHEADS, 2), blk, FL_SMEM>>>(qc, qp, qkv + NH_, vt, r,
                                                       opart, ml, 3*NH_);
    combine_k<<<B_ * NHEADS * S_ / 8, blk>>>(opart, ml, attn);

    cudaStreamWaitEvent(0, e3, 0);
    hgemm<128,2,4,0,0><<<dim3(8,32,1), blk, HG_SMEM>>>(
        attn, WoT, tmp, nullptr, nullptr, nullptr, nullptr, NH_, NH_, NH_, E_,
        1, Z0,Z0,Z0,Z0,Z0,Z0, 0, 1.f);
    ln_k<<<M, 256>>>(tmp, nullptr, x, ln1g, ln1b, h1, h1h);
    cudaEventRecord(eLN, 0);

    // ---- FFN split halves, pipelined across stream0 and s1 ----
    // stream0: FFN1a (inner cols 0..2047) -> FFN2a (K 0..2047 -> tmp)
    hgemm<128,2,4,0,1><<<dim3(16,32,1), blk, HG_SMEM>>>(
        h1h, WiT, inner, bi, nullptr, nullptr, nullptr, E_, E_, E_, F_,
        1, Z0,Z0,Z0,Z0,Z0,Z0, 1, 1.f);
    hgemm<128,2,4,0,0><<<dim3(8,32,1), blk, HG_SMEM>>>(
        inner, WoutT, tmp, nullptr, nullptr, nullptr, nullptr, 2048, F_, F_, E_,
        1, Z0,Z0,Z0,Z0,Z0,Z0, 0, 1.f);

    // s1: FFN1b (inner cols 2048..4095) -> FFN2b (K 2048..4095 -> tmp2 +bout)
    cudaStreamWaitEvent(s1, eLN, 0);
    hgemm<128,2,4,0,1><<<dim3(16,32,1), blk, HG_SMEM, s1>>>(
        h1h, WiT + 2048 * 1024, inner + 2048, bi + 2048, nullptr, nullptr, nullptr,
        E_, E_, E_, F_,
        1, Z0,Z0,Z0,Z0,Z0,Z0, 1, 1.f);
    hgemm<128,2,4,0,0><<<dim3(8,32,1), blk, HG_SMEM, s1>>>(
        inner + 2048, WoutT + 2048, tmp2, bout, nullptr, nullptr, nullptr,
        2048, F_, F_, E_,
        1, Z0,Z0,Z0,Z0,Z0,Z0, 0, 1.f);
    cudaEventRecord(eFB, s1);

    cudaStreamWaitEvent(0, eFB, 0);
    ln_k<<<M, 256>>>(tmp, tmp2, h1, ln2g, ln2b, out, nullptr);
}

// round 17
// speedup vs baseline: 1.0759x; 1.0118x over previous
#include <cuda_runtime.h>
#include <cuda_fp16.h>
#include <math.h>
#include <stdint.h>

#define B_      4
#define S_      1024
#define E_      1024
#define NHEADS  16
#define H_      64
#define NH_     1024
#define F_      4096
#define R_      2048

// ---------------- scratch (static device globals) ----------------
__device__ __half g_xh[4194304];
__device__ __half g_rpeh[8388608];
__device__ __half g_qkv[12582912];     // [B,S,3NH]
__device__ __half g_qc[4194304];
__device__ __half g_qp[4194304];
__device__ __half g_r[8388608];
__device__ __half g_attn[4194304];
__device__ float  g_opart[8388608];    // [2][z*S + i][H]
__device__ float  g_ml[262144];        // [2][row][m,l]
__device__ float  g_h1[4194304];
__device__ __half g_h1h[4194304];
__device__ __half g_inner[16777216];
__device__ float  g_tmp[4194304];
__device__ float  g_tmp2[4194304];
__device__ __half g_WqkvT[3145728];
__device__ __half g_WrT[1048576];
__device__ __half g_WoT[1048576];
__device__ __half g_WiT[4194304];
__device__ __half g_WoutT[4194304];

// ---------------- helpers ----------------
__device__ __forceinline__ uint32_t smem_u32(const void* p) {
    uint32_t a;
    asm("{ .reg .u64 t; cvta.to.shared.u64 t, %1; cvt.u32.u64 %0, t; }" : "=r"(a) : "l"(p));
    return a;
}
__device__ __forceinline__ void cpasync16(uint32_t s, const void* g) {
    asm volatile("cp.async.cg.shared.global [%0], [%1], 16;" :: "r"(s), "l"(g));
}
#define CP_COMMIT() asm volatile("cp.async.commit_group;" ::: "memory")
#define CP_WAIT(n)  asm volatile("cp.async.wait_group %0;" :: "n"(n) : "memory")

#define LDM4(r0, r1, r2, r3, a)                                                     \
    asm volatile("ldmatrix.sync.aligned.m8n8.x4.shared.b16 {%0,%1,%2,%3}, [%4];"    \
                 : "=r"(r0), "=r"(r1), "=r"(r2), "=r"(r3) : "r"(a))

#define LDM4T(r0, r1, r2, r3, a)                                                    \
    asm volatile("ldmatrix.sync.aligned.m8n8.x4.trans.shared.b16 {%0,%1,%2,%3}, [%4];" \
                 : "=r"(r0), "=r"(r1), "=r"(r2), "=r"(r3) : "r"(a))

#define MMA16816(c, a, b)                                                           \
    asm volatile("mma.sync.aligned.m16n8k16.row.col.f32.f16.f16.f32 "               \
                 "{%0,%1,%2,%3},{%4,%5,%6,%7},{%8,%9},{%0,%1,%2,%3};"               \
                 : "+f"((c)[0]), "+f"((c)[1]), "+f"((c)[2]), "+f"((c)[3])           \
                 : "r"((a)[0]), "r"((a)[1]), "r"((a)[2]), "r"((a)[3]),              \
                   "r"((b)[0]), "r"((b)[1]))

// exp on FMA/ALU pipes; common-mode error cancels in softmax normalization.
__device__ __forceinline__ float fast_exp(float x) {
    float t = fmaxf(x * 1.44269504f, -126.f);
    float fl = floorf(t);
    float f = t - fl;
    float p = fmaf(f, 0.0792345f, 0.2248712f);
    p = fmaf(f, p, 0.6958943f);
    p = fmaf(f, p, 1.0f);
    return __int_as_float(__float_as_int(p) + (((int)fl) << 23));
}

// ---------------- fp16 tensor-core GEMM, K-chunk 64, 3-stage ring ---------------
#define LDSG 72
#define HG_SMEM (3 * (128 + 128) * LDSG * 2)
template<int BN, int WRM, int WRN, int EPI, int OUTH>
__global__ __launch_bounds__(256, 2) void hgemm(
    const __half* __restrict__ A, const __half* __restrict__ Bm,
    void* __restrict__ Cv, const float* __restrict__ bias,
    const float* __restrict__ pb, __half* __restrict__ qcp, __half* __restrict__ qpp,
    int K, int lda, int ldb, int ldc, int zdiv,
    long long As1, long long As2, long long Bs1, long long Bs2,
    long long Cs1, long long Cs2, int relu, float scale)
{
    constexpr int BM = 128;
    constexpr int MW = BM / WRM, NW = BN / WRN;
    constexpr int MT = MW / 16, NPAIR = NW / 16, NT = NW / 8;
    extern __shared__ __half hsm[];
    __half* sA = hsm;
    __half* sB = hsm + 3 * BM * LDSG;

    const int bm = blockIdx.y * BM, bn = blockIdx.x * BN;
    {
        int z = blockIdx.z, zq = z / zdiv, zr = z % zdiv;
        A  += zq * As1 + zr * As2;
        Bm += zq * Bs1 + zr * Bs2;
    }
    const int tid = threadIdx.x, lane = tid & 31, wid = tid >> 5;
    const int wm = (wid / WRN) * MW, wn = (wid % WRN) * NW;

    float cf[MT][NT][4];
#pragma unroll
    for (int i = 0; i < MT; i++)
#pragma unroll
        for (int j = 0; j < NT; j++)
#pragma unroll
            for (int e = 0; e < 4; e++) cf[i][j][e] = 0.f;

    auto stage = [&](int c, int sx) {
        __half* dA = sA + sx * BM * LDSG;
        __half* dB = sB + sx * BN * LDSG;
#pragma unroll
        for (int i = 0; i < BM * 8 / 256; i++) {
            int id = tid + i * 256, row = id >> 3, ch = id & 7;
            cpasync16(smem_u32(dA + row * LDSG + ch * 8),
                      A + (long long)(bm + row) * lda + c * 64 + ch * 8);
        }
#pragma unroll
        for (int i = 0; i < BN * 8 / 256; i++) {
            int id = tid + i * 256, row = id >> 3, ch = id & 7;
            cpasync16(smem_u32(dB + row * LDSG + ch * 8),
                      Bm + (long long)(bn + row) * ldb + c * 64 + ch * 8);
        }
        CP_COMMIT();
    };

    const int nkt = K >> 6;
    stage(0, 0);
    stage(1, 1);
    int cbuf = 0, pbuf = 2;
    for (int c = 0; c < nkt; c++) {
        CP_WAIT(1);
        __syncthreads();
        if (c + 2 < nkt) stage(c + 2, pbuf);
        else CP_COMMIT();
        const uint32_t a0 = smem_u32(sA + cbuf * BM * LDSG);
        const uint32_t b0 = smem_u32(sB + cbuf * BN * LDSG);
#pragma unroll
        for (int ks = 0; ks < 4; ks++) {
            uint32_t af[MT][4], bf[NT][2];
#pragma unroll
            for (int mt = 0; mt < MT; mt++) {
                uint32_t ad = a0 + ((wm + mt * 16 + (lane & 15)) * LDSG
                                    + ks * 16 + (lane >> 4) * 8) * 2;
                LDM4(af[mt][0], af[mt][1], af[mt][2], af[mt][3], ad);
            }
#pragma unroll
            for (int p = 0; p < NPAIR; p++) {
                int rn = wn + p * 16 + (lane & 7) + ((lane >> 4) << 3);
                uint32_t bd = b0 + (rn * LDSG + ks * 16 + ((lane >> 3) & 1) * 8) * 2;
                uint32_t r0, r1, r2, r3;
                LDM4(r0, r1, r2, r3, bd);
                bf[2 * p][0] = r0; bf[2 * p][1] = r1;
                bf[2 * p + 1][0] = r2; bf[2 * p + 1][1] = r3;
            }
#pragma unroll
            for (int mt = 0; mt < MT; mt++)
#pragma unroll
                for (int nt = 0; nt < NT; nt++)
                    MMA16816(cf[mt][nt], af[mt], bf[nt]);
        }
        cbuf = cbuf == 2 ? 0 : cbuf + 1;
        pbuf = pbuf == 2 ? 0 : pbuf + 1;
    }

    long long coff;
    {
        int z = blockIdx.z, zq = z / zdiv, zr = z % zdiv;
        coff = zq * Cs1 + zr * Cs2;
    }
#pragma unroll
    for (int mt = 0; mt < MT; mt++) {
#pragma unroll
        for (int nt = 0; nt < NT; nt++) {
            int r = bm + wm + mt * 16 + (lane >> 2);
            int col = bn + wn + nt * 8 + (lane & 3) * 2;
#pragma unroll
            for (int e2 = 0; e2 < 2; e2++) {
                int row = r + 8 * e2;
                float v0 = cf[mt][nt][e2 * 2] * scale;
                float v1 = cf[mt][nt][e2 * 2 + 1] * scale;
                if (EPI == 2) {
                    if (col < NH_) {
                        float c0 = bias[col], c1 = bias[col + 1];
                        float p0 = pb[col],  p1 = pb[col + 1];
                        *(__half2*)(qcp + (long long)row * NH_ + col) =
                            __floats2half2_rn((v0 + c0) * 0.125f, (v1 + c1) * 0.125f);
                        *(__half2*)(qpp + (long long)row * NH_ + col) =
                            __floats2half2_rn((v0 + p0) * 0.125f, (v1 + p1) * 0.125f);
                    } else {
                        __half* Ch = (__half*)Cv;
                        *(__half2*)(Ch + (long long)row * ldc + col) =
                            __floats2half2_rn(v0, v1);
                    }
                } else {
                    if (bias) { v0 += bias[col]; v1 += bias[col + 1]; }
                    if (relu) { v0 = fmaxf(v0, 0.f); v1 = fmaxf(v1, 0.f); }
                    if (OUTH) {
                        __half* Ch = (__half*)Cv + coff;
                        *(__half2*)(Ch + (long long)row * ldc + col) =
                            __floats2half2_rn(v0, v1);
                    } else {
                        float* Cf = (float*)Cv + coff;
                        *(float2*)(Cf + (long long)row * ldc + col) = make_float2(v0, v1);
                    }
                }
            }
        }
    }
}

// ---------------- flash attention, split-KV halves, V via ldmatrix.trans --------
#define LDQ_  72
#define LDS_S 132
#define LDP_  136
#define FL_SMEM (4*128*LDQ_*2 + 256*LDQ_*2 + 128*LDS_S*4 + 128*LDP_*2 + 3*128*4)

__global__ __launch_bounds__(256, 1) void flash_k(
    const __half* __restrict__ qc, const __half* __restrict__ qp,
    const __half* __restrict__ kk, const __half* __restrict__ vv,
    const __half* __restrict__ rr, float* __restrict__ opart,
    float* __restrict__ ml, int kstr)
{
    extern __shared__ char smraw[];
    __half* sQc = (__half*)smraw;
    __half* sQp = sQc + 128 * LDQ_;
    __half* sK  = sQp + 128 * LDQ_;
    __half* sV  = sK  + 128 * LDQ_;          // [128 j][72 h] natural layout
    __half* sR  = sV  + 128 * LDQ_;
    float*  sS  = (float*)(sR + 256 * LDQ_);
    __half* sP  = (__half*)(sS + 128 * LDS_S);
    float*  sM  = (float*)(sP + 128 * LDP_);
    float*  sL  = sM + 128;
    float*  sAl = sL + 128;

    const int it = blockIdx.x, z = blockIdx.y, hfk = blockIdx.z;
    const int b = z >> 4, n = z & 15;
    const int i0 = it * 128;
    const int jbeg = hfk * 4, jend = jbeg + 4;
    const int tid = threadIdx.x, lane = tid & 31, wid = tid >> 5;
    const int wm = wid * 16;

    int ntlo0 = (105 - wm + 7) >> 3; if (ntlo0 < 0) ntlo0 = 0;
    int nthi1 = (126 - wm) >> 3;

    const __half* qcb = qc + (long long)b * S_ * NH_ + n * H_;
    const __half* qpb = qp + (long long)b * S_ * NH_ + n * H_;
    const __half* kb  = kk + (long long)b * S_ * kstr + n * H_;
    const __half* vb  = vv + (long long)b * S_ * kstr + n * H_;
    const __half* rb  = rr + (long long)b * R_ * NH_ + n * H_;

    auto stageK = [&](int jt) {
        const int j0 = jt * 128;
        if (jt < jend) {
#pragma unroll
            for (int i = 0; i < 4; i++) {
                int id = tid + i * 256, row = id >> 3, ch = id & 7;
                cpasync16(smem_u32(sK + row * LDQ_ + ch * 8),
                          kb + (long long)(j0 + row) * kstr + ch * 8);
            }
        }
        CP_COMMIT();
    };
    auto stageR = [&](int jt) {
        const int base = S_ + jt * 128 - i0 - 127;
        if (jt < jend) {
#pragma unroll
            for (int i = 0; i < 8; i++) {
                int id = tid + i * 256, row = id >> 3, ch = id & 7;
                int grow = base + row; grow = grow < R_ ? grow : R_ - 1;
                cpasync16(smem_u32(sR + row * LDQ_ + ch * 8),
                          rb + (long long)grow * NH_ + ch * 8);
            }
        }
        CP_COMMIT();
    };
    auto stageV = [&](int jt) {
        const int j0 = jt * 128;
        if (jt < jend) {
#pragma unroll
            for (int i = 0; i < 4; i++) {
                int id = tid + i * 256, row = id >> 3, ch = id & 7;
                cpasync16(smem_u32(sV + row * LDQ_ + ch * 8),
                          vb + (long long)(j0 + row) * kstr + ch * 8);
            }
        }
        CP_COMMIT();
    };

#pragma unroll
    for (int i = 0; i < 4; i++) {
        int id = tid + i * 256, row = id >> 3, ch = id & 7;
        cpasync16(smem_u32(sQc + row * LDQ_ + ch * 8),
                  qcb + (long long)(i0 + row) * NH_ + ch * 8);
        cpasync16(smem_u32(sQp + row * LDQ_ + ch * 8),
                  qpb + (long long)(i0 + row) * NH_ + ch * 8);
    }
    stageK(jbeg);
    stageR(jbeg);
    stageV(jbeg);
    if (tid < 128) { sM[tid] = -1e30f; sL[tid] = 0.f; }

    float of[8][4];
#pragma unroll
    for (int nt = 0; nt < 8; nt++)
#pragma unroll
        for (int e = 0; e < 4; e++) of[nt][e] = 0.f;

    const uint32_t aQc = smem_u32(sQc), aQp = smem_u32(sQp);
    const uint32_t aK = smem_u32(sK), aV = smem_u32(sV);
    const uint32_t aR = smem_u32(sR), aP = smem_u32(sP);

    for (int jt = jbeg; jt < jend; jt++) {
        CP_WAIT(2);
        __syncthreads();

        // ---- content scores -> sS ----
        float cf[16][4];
#pragma unroll
        for (int nt = 0; nt < 16; nt++)
#pragma unroll
            for (int e = 0; e < 4; e++) cf[nt][e] = 0.f;
#pragma unroll
        for (int ks = 0; ks < 4; ks++) {
            uint32_t af[4], bf[16][2];
            LDM4(af[0], af[1], af[2], af[3],
                 aQc + ((wm + (lane & 15)) * LDQ_ + ks * 16 + (lane >> 4) * 8) * 2);
#pragma unroll
            for (int p = 0; p < 8; p++) {
                int rn = p * 16 + (lane & 7) + ((lane >> 4) << 3);
                uint32_t r0, r1, r2, r3;
                LDM4(r0, r1, r2, r3, aK + (rn * LDQ_ + ks * 16 + ((lane >> 3) & 1) * 8) * 2);
                bf[2 * p][0] = r0; bf[2 * p][1] = r1;
                bf[2 * p + 1][0] = r2; bf[2 * p + 1][1] = r3;
            }
#pragma unroll
            for (int nt = 0; nt < 16; nt++) MMA16816(cf[nt], af, bf[nt]);
        }
#pragma unroll
        for (int nt = 0; nt < 16; nt++) {
            int c0 = nt * 8 + (lane & 3) * 2;
#pragma unroll
            for (int e2 = 0; e2 < 2; e2++) {
                int row = wm + (lane >> 2) + 8 * e2;
                *(float2*)&sS[row * LDS_S + c0] = make_float2(cf[nt][e2 * 2], cf[nt][e2 * 2 + 1]);
            }
        }

        CP_WAIT(1);
        __syncthreads();
        stageK(jt + 1);

        // ---- position scores, band tiles only ----
#pragma unroll
        for (int halfg = 0; halfg < 2; halfg++) {
            int g0 = halfg * 128;
            int lo = halfg == 0 ? ntlo0 : 0;
            int hi = halfg == 0 ? 15 : nthi1;
#pragma unroll
            for (int nt = 0; nt < 16; nt++)
#pragma unroll
                for (int e = 0; e < 4; e++) cf[nt][e] = 0.f;
#pragma unroll
            for (int ks = 0; ks < 4; ks++) {
                uint32_t af[4], bf[16][2];
                LDM4(af[0], af[1], af[2], af[3],
                     aQp + ((wm + (lane & 15)) * LDQ_ + ks * 16 + (lane >> 4) * 8) * 2);
#pragma unroll
                for (int p = 0; p < 8; p++) {
                    if (2 * p + 1 < lo || 2 * p > hi) continue;
                    int rn = g0 + p * 16 + (lane & 7) + ((lane >> 4) << 3);
                    uint32_t r0, r1, r2, r3;
                    LDM4(r0, r1, r2, r3, aR + (rn * LDQ_ + ks * 16 + ((lane >> 3) & 1) * 8) * 2);
                    bf[2 * p][0] = r0; bf[2 * p][1] = r1;
                    bf[2 * p + 1][0] = r2; bf[2 * p + 1][1] = r3;
                }
#pragma unroll
                for (int nt = 0; nt < 16; nt++) {
                    if (nt < lo || nt > hi) continue;
                    MMA16816(cf[nt], af, bf[nt]);
                }
            }
#pragma unroll
            for (int nt = 0; nt < 16; nt++) {
                if (nt < lo || nt > hi) continue;
#pragma unroll
                for (int e = 0; e < 4; e++) {
                    int li = wm + (lane >> 2) + 8 * (e >> 1);
                    int g  = g0 + nt * 8 + (lane & 3) * 2 + (e & 1);
                    int lj = g - 127 + li;
                    if (lj >= 0 && lj < 128) sS[li * LDS_S + lj] += cf[nt][e];
                }
            }
            __syncwarp();
        }

        CP_WAIT(1);
        __syncthreads();
        stageR(jt + 1);

        // ---- online softmax ----
        {
            int rloc = wm + (lane >> 1), hf = lane & 1;
            float* srow = &sS[rloc * LDS_S + hf * 64];
            float4* srow4 = (float4*)srow;
            float m0 = -1e30f, m1 = -1e30f, m2 = -1e30f, m3 = -1e30f;
#pragma unroll
            for (int c = 0; c < 16; c += 2) {
                float4 a = srow4[c], bq = srow4[c + 1];
                m0 = fmaxf(m0, fmaxf(a.x, a.y));
                m1 = fmaxf(m1, fmaxf(a.z, a.w));
                m2 = fmaxf(m2, fmaxf(bq.x, bq.y));
                m3 = fmaxf(m3, fmaxf(bq.z, bq.w));
            }
            float mx = fmaxf(fmaxf(m0, m1), fmaxf(m2, m3));
            mx = fmaxf(mx, __shfl_xor_sync(0xffffffffu, mx, 1));
            float mold = sM[rloc];
            float mnew = fmaxf(mold, mx);
            float alpha = fast_exp(mold - mnew);
            float s0 = 0.f, s1 = 0.f;
            __half* prow = &sP[rloc * LDP_ + hf * 64];
#pragma unroll
            for (int c = 0; c < 16; c++) {
                float4 a = srow4[c];
                float p0 = fast_exp(a.x - mnew);
                float p1 = fast_exp(a.y - mnew);
                float p2 = fast_exp(a.z - mnew);
                float p3 = fast_exp(a.w - mnew);
                s0 += p0 + p1;
                s1 += p2 + p3;
                *(__half2*)&prow[c * 4]     = __floats2half2_rn(p0, p1);
                *(__half2*)&prow[c * 4 + 2] = __floats2half2_rn(p2, p3);
            }
            float sum = s0 + s1;
            sum += __shfl_xor_sync(0xffffffffu, sum, 1);
            if (hf == 0) {
                sL[rloc] = sL[rloc] * alpha + sum;
                sM[rloc] = mnew;
                sAl[rloc] = alpha;
            }
        }
        __syncwarp();

        // ---- rescale O, PV mma (B from natural-layout V via ldmatrix.trans) ----
#pragma unroll
        for (int e2 = 0; e2 < 2; e2++) {
            float al = sAl[wm + (lane >> 2) + 8 * e2];
#pragma unroll
            for (int nt = 0; nt < 8; nt++) {
                of[nt][e2 * 2]     *= al;
                of[nt][e2 * 2 + 1] *= al;
            }
        }
#pragma unroll
        for (int ks = 0; ks < 8; ks++) {
            uint32_t af[4], bfv[8][2];
            LDM4(af[0], af[1], af[2], af[3],
                 aP + ((wm + (lane & 15)) * LDP_ + ks * 16 + (lane >> 4) * 8) * 2);
#pragma unroll
            for (int p = 0; p < 4; p++) {
                // V tile is [j(k), h(n)]: row = k, col = n; .trans restores B layout
                uint32_t bd = aV + ((ks * 16 + (lane & 7) + ((lane >> 3) & 1) * 8) * LDQ_
                                    + p * 16 + (lane >> 4) * 8) * 2;
                uint32_t r0, r1, r2, r3;
                LDM4T(r0, r1, r2, r3, bd);
                bfv[2 * p][0] = r0; bfv[2 * p][1] = r1;
                bfv[2 * p + 1][0] = r2; bfv[2 * p + 1][1] = r3;
            }
#pragma unroll
            for (int nt = 0; nt < 8; nt++) MMA16816(of[nt], af, bfv[nt]);
        }
        __syncthreads();
        stageV(jt + 1);
    }

    long long hoff = (long long)hfk * 4194304;
#pragma unroll
    for (int e2 = 0; e2 < 2; e2++) {
        int li = wm + (lane >> 2) + 8 * e2;
        long long rowg = (long long)z * S_ + i0 + li;
#pragma unroll
        for (int nt = 0; nt < 8; nt++) {
            int col = nt * 8 + (lane & 3) * 2;
            *(float2*)(opart + hoff + rowg * H_ + col) =
                make_float2(of[nt][e2 * 2], of[nt][e2 * 2 + 1]);
        }
        if ((lane & 3) == 0) {
            ml[(long long)hfk * 131072 + rowg * 2]     = sM[li];
            ml[(long long)hfk * 131072 + rowg * 2 + 1] = sL[li];
        }
    }
}

// ---------------- split-KV combine ----------------------------------------------
__global__ __launch_bounds__(256) void combine_k(
    const float* __restrict__ opart, const float* __restrict__ ml,
    __half* __restrict__ attn)
{
    int row = blockIdx.x * 8 + (threadIdx.x >> 5);
    int lane = threadIdx.x & 31;
    int z = row >> 10, i = row & 1023;
    int b = z >> 4, n = z & 15;
    float m1 = ml[row * 2],          l1 = ml[row * 2 + 1];
    float m2 = ml[131072 + row * 2], l2 = ml[131072 + row * 2 + 1];
    float m = fmaxf(m1, m2);
    float a1 = fast_exp(m1 - m), a2 = fast_exp(m2 - m);
    float inv = 1.0f / fmaf(a1, l1, a2 * l2);
    float2 v1 = *(const float2*)(opart + (long long)row * H_ + lane * 2);
    float2 v2 = *(const float2*)(opart + 4194304 + (long long)row * H_ + lane * 2);
    float o0 = fmaf(a1, v1.x, a2 * v2.x) * inv;
    float o1 = fmaf(a1, v1.y, a2 * v2.y) * inv;
    *(__half2*)(attn + (long long)(b * S_ + i) * NH_ + n * H_ + lane * 2) =
        __floats2half2_rn(o0, o1);
}

// ---------------- fp32 -> fp16 copy ----------------
__global__ __launch_bounds__(256) void f2h_k(const float* __restrict__ in,
                                             __half* __restrict__ out)
{
    long long i = (long long)blockIdx.x * 256 + threadIdx.x;
    float4 v = ((const float4*)in)[i];
    ((__half2*)out)[i * 2]     = __floats2half2_rn(v.x, v.y);
    ((__half2*)out)[i * 2 + 1] = __floats2half2_rn(v.z, v.w);
}

// ---------------- fp32 transpose -> fp16 ----------------
__global__ void transpose_h16(const float* __restrict__ in, __half* __restrict__ out,
                              int rows, int cols)
{
    __shared__ float tile[32][33];
    int r0 = blockIdx.y * 32, c0 = blockIdx.x * 32;
    int tx = threadIdx.x, ty = threadIdx.y;
#pragma unroll
    for (int i = 0; i < 4; i++)
        tile[ty + i * 8][tx] = in[(long long)(r0 + ty + i * 8) * cols + c0 + tx];
    __syncthreads();
#pragma unroll
    for (int i = 0; i < 4; i++)
        out[(long long)(c0 + ty + i * 8) * rows + r0 + tx] = __float2half_rn(tile[tx][ty + i * 8]);
}

// ---------------- residual + LayerNorm (a [+a2] + res; optional fp16 copy) ------
__global__ __launch_bounds__(256) void ln_k(
    const float* __restrict__ a, const float* __restrict__ a2,
    const float* __restrict__ res,
    const float* __restrict__ g, const float* __restrict__ bt,
    float* __restrict__ o, __half* __restrict__ oh)
{
    __shared__ float red[16];
    long long row = blockIdx.x;
    int t = threadIdx.x;
    float4 va = *((const float4*)(a + row * 1024) + t);
    float4 vr = *((const float4*)(res + row * 1024) + t);
    float4 x;
    x.x = va.x + vr.x; x.y = va.y + vr.y; x.z = va.z + vr.z; x.w = va.w + vr.w;
    if (a2) {
        float4 v2 = *((const float4*)(a2 + row * 1024) + t);
        x.x += v2.x; x.y += v2.y; x.z += v2.z; x.w += v2.w;
    }
    float s  = x.x + x.y + x.z + x.w;
    float q2 = x.x * x.x + x.y * x.y + x.z * x.z + x.w * x.w;
#pragma unroll
    for (int off = 16; off; off >>= 1) {
        s  += __shfl_xor_sync(0xffffffffu, s, off);
        q2 += __shfl_xor_sync(0xffffffffu, q2, off);
    }
    if ((t & 31) == 0) { red[t >> 5] = s; red[8 + (t >> 5)] = q2; }
    __syncthreads();
    if (t == 0) {
        float ss = red[0], qq = red[8];
#pragma unroll
        for (int i = 1; i < 8; i++) { ss += red[i]; qq += red[8 + i]; }
        red[0] = ss; red[8] = qq;
    }
    __syncthreads();
    float mu  = red[0] * (1.f / 1024.f);
    float var = red[8] * (1.f / 1024.f) - mu * mu;
    float rs = rsqrtf(var + 1e-12f);
    float4 gg = *((const float4*)g + t);
    float4 bb = *((const float4*)bt + t);
    float4 y;
    y.x = (x.x - mu) * rs * gg.x + bb.x;
    y.y = (x.y - mu) * rs * gg.y + bb.y;
    y.z = (x.z - mu) * rs * gg.z + bb.z;
    y.w = (x.w - mu) * rs * gg.w + bb.w;
    *((float4*)(o + row * 1024) + t) = y;
    if (oh) {
        __half2* ph = (__half2*)(oh + row * 1024);
        ph[2 * t]     = __floats2half2_rn(y.x, y.y);
        ph[2 * t + 1] = __floats2half2_rn(y.z, y.w);
    }
}

// ---------------- driver --------------------------------------------------------
extern "C" void kernel_launch(void* const* d_in, const int* in_sizes, int n_in,
                              void* d_out, int out_size)
{
    const float* x    = (const float*)d_in[0];
    const float* cb   = (const float*)d_in[1];
    const float* pb   = (const float*)d_in[2];
    const float* rpe  = (const float*)d_in[3];
    const float* Wq   = (const float*)d_in[4];
    const float* Wk   = (const float*)d_in[5];
    const float* Wv   = (const float*)d_in[6];
    const float* Wr   = (const float*)d_in[7];
    const float* Wo   = (const float*)d_in[8];
    const float* ln1g = (const float*)d_in[9];
    const float* ln1b = (const float*)d_in[10];
    const float* Wi   = (const float*)d_in[11];
    const float* bi   = (const float*)d_in[12];
    const float* Wout = (const float*)d_in[13];
    const float* bout = (const float*)d_in[14];
    const float* ln2g = (const float*)d_in[15];
    const float* ln2b = (const float*)d_in[16];
    float* out = (float*)d_out;

    __half *xh,*rpeh,*qkv,*qc,*qp,*r,*attn,*h1h,*inner;
    __half *WqkvT,*WrT,*WoT,*WiT,*WoutT;
    float *h1,*tmp,*tmp2,*opart,*ml;
    cudaGetSymbolAddress((void**)&xh, g_xh);      cudaGetSymbolAddress((void**)&rpeh, g_rpeh);
    cudaGetSymbolAddress((void**)&qkv, g_qkv);    cudaGetSymbolAddress((void**)&qc, g_qc);
    cudaGetSymbolAddress((void**)&qp, g_qp);      cudaGetSymbolAddress((void**)&r, g_r);
    cudaGetSymbolAddress((void**)&attn, g_attn);
    cudaGetSymbolAddress((void**)&opart, g_opart);cudaGetSymbolAddress((void**)&ml, g_ml);
    cudaGetSymbolAddress((void**)&h1, g_h1);      cudaGetSymbolAddress((void**)&h1h, g_h1h);
    cudaGetSymbolAddress((void**)&inner, g_inner);cudaGetSymbolAddress((void**)&tmp, g_tmp);
    cudaGetSymbolAddress((void**)&tmp2, g_tmp2);
    cudaGetSymbolAddress((void**)&WqkvT, g_WqkvT);cudaGetSymbolAddress((void**)&WrT, g_WrT);
    cudaGetSymbolAddress((void**)&WoT, g_WoT);    cudaGetSymbolAddress((void**)&WiT, g_WiT);
    cudaGetSymbolAddress((void**)&WoutT, g_WoutT);

    cudaFuncSetAttribute((const void*)hgemm<128,2,4,0,1>,
                         cudaFuncAttributeMaxDynamicSharedMemorySize, HG_SMEM);
    cudaFuncSetAttribute((const void*)hgemm<128,2,4,0,0>,
                         cudaFuncAttributeMaxDynamicSharedMemorySize, HG_SMEM);
    cudaFuncSetAttribute((const void*)hgemm<128,2,4,2,1>,
                         cudaFuncAttributeMaxDynamicSharedMemorySize, HG_SMEM);
    cudaFuncSetAttribute(flash_k, cudaFuncAttributeMaxDynamicSharedMemorySize, FL_SMEM);

    static cudaStream_t s1 = nullptr, s2 = nullptr, s3 = nullptr;
    static cudaEvent_t  eF = nullptr, e1 = nullptr, e2 = nullptr, e3 = nullptr;
    static cudaEvent_t  eLN = nullptr, eFB = nullptr;
    if (s1 == nullptr) {
        cudaStreamCreateWithFlags(&s1, cudaStreamNonBlocking);
        cudaStreamCreateWithFlags(&s2, cudaStreamNonBlocking);
        cudaStreamCreateWithFlags(&s3, cudaStreamNonBlocking);
        cudaEventCreateWithFlags(&eF, cudaEventDisableTiming);
        cudaEventCreateWithFlags(&e1, cudaEventDisableTiming);
        cudaEventCreateWithFlags(&e2, cudaEventDisableTiming);
        cudaEventCreateWithFlags(&e3, cudaEventDisableTiming);
        cudaEventCreateWithFlags(&eLN, cudaEventDisableTiming);
        cudaEventCreateWithFlags(&eFB, cudaEventDisableTiming);
    }

    const int M = B_ * S_;
    dim3 blk(256);
    const long long Z0 = 0;

    cudaEventRecord(eF, 0);
    cudaStreamWaitEvent(s1, eF, 0);
    cudaStreamWaitEvent(s2, eF, 0);
    cudaStreamWaitEvent(s3, eF, 0);

    f2h_k<<<M * E_ / 1024, blk>>>(x, xh);

    transpose_h16<<<dim3(32, 32), dim3(32, 8), 0, s1>>>(Wq, WqkvT,               E_, NH_);
    transpose_h16<<<dim3(32, 32), dim3(32, 8), 0, s1>>>(Wk, WqkvT + 1024 * 1024, E_, NH_);
    transpose_h16<<<dim3(32, 32), dim3(32, 8), 0, s1>>>(Wv, WqkvT + 2048 * 1024, E_, NH_);
    cudaEventRecord(e1, s1);

    f2h_k<<<B_ * R_ * E_ / 1024, blk, 0, s2>>>(rpe, rpeh);
    transpose_h16<<<dim3(32, 32), dim3(32, 8), 0, s2>>>(Wr, WrT, E_, NH_);
    hgemm<128,2,4,0,1><<<dim3(8,64,1), blk, HG_SMEM, s2>>>(
        rpeh, WrT, r, nullptr, nullptr, nullptr, nullptr, E_, E_, E_, NH_,
        1, Z0,Z0,Z0,Z0,Z0,Z0, 0, 1.f);
    cudaEventRecord(e2, s2);

    transpose_h16<<<dim3(32, 32),  dim3(32, 8), 0, s3>>>(Wo,   WoT,   NH_, E_);
    transpose_h16<<<dim3(128, 32), dim3(32, 8), 0, s3>>>(Wi,   WiT,   E_, F_);
    transpose_h16<<<dim3(32, 128), dim3(32, 8), 0, s3>>>(Wout, WoutT, F_, E_);
    cudaEventRecord(e3, s3);

    cudaStreamWaitEvent(0, e1, 0);
    hgemm<128,2,4,2,1><<<dim3(24,32,1), blk, HG_SMEM>>>(
        xh, WqkvT, qkv, cb, pb, qc, qp, E_, E_, E_, 3*NH_,
        1, Z0,Z0,Z0,Z0,Z0,Z0, 0, 1.f);

    // split-KV flash (V consumed in natural layout via ldmatrix.trans), then merge
    cudaStreamWaitEvent(0, e2, 0);
    flash_k<<<dim3(8, B_ * NHEADS, 2), blk, FL_SMEM>>>(qc, qp, qkv + NH_, qkv + 2*NH_,
                                                       r, opart, ml, 3*NH_);
    combine_k<<<B_ * NHEADS * S_ / 8, blk>>>(opart, ml, attn);

    cudaStreamWaitEvent(0, e3, 0);
    hgemm<128,2,4,0,0><<<dim3(8,32,1), blk, HG_SMEM>>>(
        attn, WoT, tmp, nullptr, nullptr, nullptr, nullptr, NH_, NH_, NH_, E_,
        1, Z0,Z0,Z0,Z0,Z0,Z0, 0, 1.f);
    ln_k<<<M, 256>>>(tmp, nullptr, x, ln1g, ln1b, h1, h1h);
    cudaEventRecord(eLN, 0);

    // ---- FFN split halves, pipelined across stream0 and s1 ----
    hgemm<128,2,4,0,1><<<dim3(16,32,1), blk, HG_SMEM>>>(
        h1h, WiT, inner, bi, nullptr, nullptr, nullptr, E_, E_, E_, F_,
        1, Z0,Z0,Z0,Z0,Z0,Z0, 1, 1.f);
    hgemm<128,2,4,0,0><<<dim3(8,32,1), blk, HG_SMEM>>>(
        inner, WoutT, tmp, nullptr, nullptr, nullptr, nullptr, 2048, F_, F_, E_,
        1, Z0,Z0,Z0,Z0,Z0,Z0, 0, 1.f);

    cudaStreamWaitEvent(s1, eLN, 0);
    hgemm<128,2,4,0,1><<<dim3(16,32,1), blk, HG_SMEM, s1>>>(
        h1h, WiT + 2048 * 1024, inner + 2048, bi + 2048, nullptr, nullptr, nullptr,
        E_, E_, E_, F_,
        1, Z0,Z0,Z0,Z0,Z0,Z0, 1, 1.f);
    hgemm<128,2,4,0,0><<<dim3(8,32,1), blk, HG_SMEM, s1>>>(
        inner + 2048, WoutT + 2048, tmp2, bout, nullptr, nullptr, nullptr,
        2048, F_, F_, E_,
        1, Z0,Z0,Z0,Z0,Z0,Z0, 0, 1.f);
    cudaEventRecord(eFB, s1);

    cudaStreamWaitEvent(0, eFB, 0);
    ln_k<<<M, 256>>>(tmp, tmp2, h1, ln2g, ln2b, out, nullptr);
}